// round 2
// baseline (speedup 1.0000x reference)
#include <cuda_runtime.h>
#include <math.h>

#define Gn 128

static const long long O_XOUT = 0LL;
static const long long O_Z    = 33554432LL;
static const long long O_ZHAT = 50331648LL;
static const long long O_SURP = 67108864LL;
static const long long O_KC   = 67371008LL;
static const long long O_VP   = 84148224LL;
static const long long O_GATE = 100925440LL;
static const long long O_QN   = 101187584LL;
static const long long O_VC   = 117964800LL;
static const long long O_WN   = 134742016LL;
static const long long O_S4   = 135004160LL;

__device__ __forceinline__ void fz(float c[4][4]) {
#pragma unroll
    for (int a = 0; a < 4; a++)
#pragma unroll
        for (int b = 0; b < 4; b++) c[a][b] = 0.f;
}

// C[64 tok][64 out] += A_smem[64][K] @ W[K][64-slice]; W row-major stride wst.
__device__ __forceinline__ void gemm_tile(
    const float* __restrict__ As, int sas, const float* __restrict__ W, int wst,
    int K, float* wsm, float c[4][4], int ty, int tx, int tid)
{
    for (int k0 = 0; k0 < K; k0 += 16) {
#pragma unroll
        for (int j = 0; j < 4; j++) {
            int flat = tid + 256 * j;
            int r = flat >> 6, col = flat & 63;
            wsm[r * 68 + col] = W[(size_t)(k0 + r) * wst + col];
        }
        __syncthreads();
#pragma unroll
        for (int i4 = 0; i4 < 4; i4++) {
            float4 a4[4];
#pragma unroll
            for (int tt = 0; tt < 4; tt++)
                a4[tt] = *(const float4*)&As[(ty * 4 + tt) * sas + k0 + i4 * 4];
#pragma unroll
            for (int ii = 0; ii < 4; ii++) {
                float4 w4 = *(const float4*)&wsm[(i4 * 4 + ii) * 68 + tx * 4];
#pragma unroll
                for (int tt = 0; tt < 4; tt++) {
                    float a = ((const float*)&a4[tt])[ii];
                    c[tt][0] = fmaf(a, w4.x, c[tt][0]);
                    c[tt][1] = fmaf(a, w4.y, c[tt][1]);
                    c[tt][2] = fmaf(a, w4.z, c[tt][2]);
                    c[tt][3] = fmaf(a, w4.w, c[tt][3]);
                }
            }
        }
        __syncthreads();
    }
}

// logits[t][s] = sum_d A[t][d] * S[s][d];  S is [slots][64] row-major.
__device__ __forceinline__ void gemm_tile_T(
    const float* __restrict__ As, int sas, const float* __restrict__ S,
    int slots, int K, float* wsm, float c[4][4], int ty, int tx, int tid)
{
    for (int k0 = 0; k0 < K; k0 += 16) {
#pragma unroll
        for (int j = 0; j < 4; j++) {
            int flat = tid + 256 * j;
            int r = flat >> 6, col = flat & 63;
            wsm[r * 68 + col] = (col < slots) ? S[col * 64 + k0 + r] : 0.f;
        }
        __syncthreads();
#pragma unroll
        for (int i4 = 0; i4 < 4; i4++) {
            float4 a4[4];
#pragma unroll
            for (int tt = 0; tt < 4; tt++)
                a4[tt] = *(const float4*)&As[(ty * 4 + tt) * sas + k0 + i4 * 4];
#pragma unroll
            for (int ii = 0; ii < 4; ii++) {
                float4 w4 = *(const float4*)&wsm[(i4 * 4 + ii) * 68 + tx * 4];
#pragma unroll
                for (int tt = 0; tt < 4; tt++) {
                    float a = ((const float*)&a4[tt])[ii];
                    c[tt][0] = fmaf(a, w4.x, c[tt][0]);
                    c[tt][1] = fmaf(a, w4.y, c[tt][1]);
                    c[tt][2] = fmaf(a, w4.z, c[tt][2]);
                    c[tt][3] = fmaf(a, w4.w, c[tt][3]);
                }
            }
        }
        __syncthreads();
    }
}

// softmax (with 0.125 scale) over SLOTS logits in buf[tok][0..SLOTS), 4 thr/token
template <int SLOTS>
__device__ __forceinline__ void softmax_q(float* buf, int tok, int jq)
{
    const int nS = SLOTS / 4;
    float l[nS];
    float m = -1e30f;
#pragma unroll
    for (int i = 0; i < nS; i++) {
        l[i] = buf[tok * 68 + jq * nS + i] * 0.125f;
        m = fmaxf(m, l[i]);
    }
    m = fmaxf(m, __shfl_xor_sync(0xffffffffu, m, 1));
    m = fmaxf(m, __shfl_xor_sync(0xffffffffu, m, 2));
    float s = 0.f;
#pragma unroll
    for (int i = 0; i < nS; i++) { l[i] = expf(l[i] - m); s += l[i]; }
    s += __shfl_xor_sync(0xffffffffu, s, 1);
    s += __shfl_xor_sync(0xffffffffu, s, 2);
    float inv = 1.f / s;
#pragma unroll
    for (int i = 0; i < nS; i++) buf[tok * 68 + jq * nS + i] = l[i] * inv;
}

__global__ void __launch_bounds__(256)
ccg_kernel(
    const float* __restrict__ x_col, const float* __restrict__ pm_state,
    const float* __restrict__ em_state, const float* __restrict__ z_hat_prev,
    const float* __restrict__ ffn_norm_w, const float* __restrict__ ffn_norm_b,
    const float* __restrict__ ffn_up_w, const float* __restrict__ ffn_up_b,
    const float* __restrict__ ffn_down_w, const float* __restrict__ ffn_down_b,
    const float* __restrict__ pm_up_w, const float* __restrict__ pm_up_b,
    const float* __restrict__ pm_down_w, const float* __restrict__ pm_down_b,
    const float* __restrict__ em_up_w, const float* __restrict__ em_up_b,
    const float* __restrict__ em_down_w, const float* __restrict__ em_down_b,
    const float* __restrict__ post_w, const float* __restrict__ post_b,
    const float* __restrict__ enc_w, const float* __restrict__ enc_b,
    const float* __restrict__ pred_w, const float* __restrict__ pred_b,
    const float* __restrict__ gain_w, const float* __restrict__ gain_b,
    float* __restrict__ out)
{
    extern __shared__ float smf[];
    float* xs  = smf;               // 64 x 132
    float* hs  = xs + 64 * 132;     // 64 x 132
    float* bA  = hs + 64 * 132;     // 64 x 68
    float* bB  = bA + 64 * 68;      // 64 x 68
    float* wsm = bB + 64 * 68;      // 16 x 68

    const int tid = threadIdx.x;
    const int ty = tid >> 4, tx = tid & 15;
    const int tok = tid >> 2, jq = tid & 3;
    const int g  = blockIdx.y;
    const int t0 = blockIdx.x * 64;
    const int bs = t0 >> 9;
    const int bidx = g >> 4;

    float c[4][4];

    // ---- load x tile ----
#pragma unroll
    for (int jj = 0; jj < 8; jj++) {
        int flat = tid + 256 * jj;           // float4 units
        int r = flat >> 5, c4 = flat & 31;
        *(float4*)&xs[r * 132 + c4 * 4] =
            *(const float4*)&x_col[((size_t)(t0 + r) * Gn + g) * 128 + c4 * 4];
    }
    __syncthreads();

    // ================= pm memory stage =================
    fz(c);
    gemm_tile(xs, 132, pm_up_w + (size_t)g * 128 * 64, 64, 128, wsm, c, ty, tx, tid);
#pragma unroll
    for (int tt = 0; tt < 4; tt++)
#pragma unroll
        for (int j = 0; j < 4; j++)
            bB[(ty * 4 + tt) * 68 + tx * 4 + j] = c[tt][j] + pm_up_b[g * 64 + tx * 4 + j];

    const float* Spm = pm_state + (size_t)((bs * 8 + bidx) * 16) * 64;
    fz(c);
    gemm_tile_T(bB, 68, Spm, 16, 64, wsm, c, ty, tx, tid);
    if (tx < 4) {
#pragma unroll
        for (int tt = 0; tt < 4; tt++)
#pragma unroll
            for (int j = 0; j < 4; j++)
                bA[(ty * 4 + tt) * 68 + tx * 4 + j] = c[tt][j];
    }
    __syncthreads();
    softmax_q<16>(bA, tok, jq);
    __syncthreads();
    fz(c);
    gemm_tile(bA, 68, Spm, 64, 16, wsm, c, ty, tx, tid);
#pragma unroll
    for (int tt = 0; tt < 4; tt++)
#pragma unroll
        for (int j = 0; j < 4; j++)
            bB[(ty * 4 + tt) * 68 + tx * 4 + j] = c[tt][j];

    for (int half = 0; half < 2; half++) {
        fz(c);
        gemm_tile(bB, 68, pm_down_w + (size_t)g * 64 * 128 + half * 64, 128, 64, wsm, c, ty, tx, tid);
#pragma unroll
        for (int tt = 0; tt < 4; tt++)
#pragma unroll
            for (int j = 0; j < 4; j++) {
                int o = half * 64 + tx * 4 + j;
                xs[(ty * 4 + tt) * 132 + o] += c[tt][j] + pm_down_b[g * 128 + o];
            }
    }
    __syncthreads();

    // ================= em memory stage =================
    fz(c);
    gemm_tile(xs, 132, em_up_w + (size_t)g * 128 * 64, 64, 128, wsm, c, ty, tx, tid);
#pragma unroll
    for (int tt = 0; tt < 4; tt++)
#pragma unroll
        for (int j = 0; j < 4; j++)
            bB[(ty * 4 + tt) * 68 + tx * 4 + j] = c[tt][j] + em_up_b[g * 64 + tx * 4 + j];

    const float* Sem = em_state + (size_t)((bs * 8 + bidx) * 64) * 64;
    fz(c);
    gemm_tile_T(bB, 68, Sem, 64, 64, wsm, c, ty, tx, tid);
#pragma unroll
    for (int tt = 0; tt < 4; tt++)
#pragma unroll
        for (int j = 0; j < 4; j++)
            bA[(ty * 4 + tt) * 68 + tx * 4 + j] = c[tt][j];
    __syncthreads();
    softmax_q<64>(bA, tok, jq);
    __syncthreads();
    fz(c);
    gemm_tile(bA, 68, Sem, 64, 64, wsm, c, ty, tx, tid);
#pragma unroll
    for (int tt = 0; tt < 4; tt++)
#pragma unroll
        for (int j = 0; j < 4; j++)
            bB[(ty * 4 + tt) * 68 + tx * 4 + j] = c[tt][j];

    for (int half = 0; half < 2; half++) {
        fz(c);
        gemm_tile(bB, 68, em_down_w + (size_t)g * 64 * 128 + half * 64, 128, 64, wsm, c, ty, tx, tid);
#pragma unroll
        for (int tt = 0; tt < 4; tt++)
#pragma unroll
            for (int j = 0; j < 4; j++) {
                int o = half * 64 + tx * 4 + j;
                xs[(ty * 4 + tt) * 132 + o] += c[tt][j] + em_down_b[g * 128 + o];
            }
    }
    __syncthreads();

    // ================= enc / delta / surprise =================
    fz(c);
    gemm_tile(xs, 132, enc_w + (size_t)g * 128 * 64, 64, 128, wsm, c, ty, tx, tid);
    {
        float sp[4];
#pragma unroll
        for (int tt = 0; tt < 4; tt++) {
            int t = ty * 4 + tt;
            size_t tg = t0 + t;
            float4 zh4 = *(const float4*)&z_hat_prev[(tg * Gn + g) * 64 + tx * 4];
            float z0 = c[tt][0] + enc_b[g * 64 + tx * 4 + 0];
            float z1 = c[tt][1] + enc_b[g * 64 + tx * 4 + 1];
            float z2 = c[tt][2] + enc_b[g * 64 + tx * 4 + 2];
            float z3 = c[tt][3] + enc_b[g * 64 + tx * 4 + 3];
            bA[t * 68 + tx * 4 + 0] = z0;
            bA[t * 68 + tx * 4 + 1] = z1;
            bA[t * 68 + tx * 4 + 2] = z2;
            bA[t * 68 + tx * 4 + 3] = z3;
            float e0 = z0 - zh4.x, e1 = z1 - zh4.y, e2 = z2 - zh4.z, e3 = z3 - zh4.w;
            bB[t * 68 + tx * 4 + 0] = e0;
            bB[t * 68 + tx * 4 + 1] = e1;
            bB[t * 68 + tx * 4 + 2] = e2;
            bB[t * 68 + tx * 4 + 3] = e3;
            sp[tt] = e0 * e0 + e1 * e1 + e2 * e2 + e3 * e3;
            *(float4*)&out[O_Z + (tg * Gn + g) * 64 + tx * 4] = make_float4(z0, z1, z2, z3);
        }
#pragma unroll
        for (int tt = 0; tt < 4; tt++) {
            sp[tt] += __shfl_xor_sync(0xffffffffu, sp[tt], 1);
            sp[tt] += __shfl_xor_sync(0xffffffffu, sp[tt], 2);
            sp[tt] += __shfl_xor_sync(0xffffffffu, sp[tt], 4);
            sp[tt] += __shfl_xor_sync(0xffffffffu, sp[tt], 8);
        }
        if (tx == 0) {
#pragma unroll
            for (int tt = 0; tt < 4; tt++) {
                size_t tg = t0 + ty * 4 + tt;
                float s = sqrtf(sp[tt]);
                out[O_SURP + tg * Gn + g] = s;
                out[O_S4 + tg * Gn + g] = s;
                out[O_GATE + tg * Gn + g] = fminf(s, 1.f);
            }
        }
    }

    // ================= gain =================
    for (int half = 0; half < 2; half++) {
        fz(c);
        gemm_tile(bB, 68, gain_w + (size_t)g * 64 * 128 + half * 64, 128, 64, wsm, c, ty, tx, tid);
#pragma unroll
        for (int tt = 0; tt < 4; tt++)
#pragma unroll
            for (int j = 0; j < 4; j++) {
                int o = half * 64 + tx * 4 + j;
                hs[(ty * 4 + tt) * 132 + o] = 1.f + 0.1f * tanhf(c[tt][j] + gain_b[g * 128 + o]);
            }
    }
    __syncthreads();

    // ================= layernorm * gain -> hs =================
    {
        float s = 0.f, sq = 0.f;
        float4 xv[8];
#pragma unroll
        for (int u = 0; u < 8; u++) {
            xv[u] = *(const float4*)&xs[tok * 132 + jq * 32 + u * 4];
            s  += xv[u].x + xv[u].y + xv[u].z + xv[u].w;
            sq += xv[u].x * xv[u].x + xv[u].y * xv[u].y + xv[u].z * xv[u].z + xv[u].w * xv[u].w;
        }
        s  += __shfl_xor_sync(0xffffffffu, s, 1);
        s  += __shfl_xor_sync(0xffffffffu, s, 2);
        sq += __shfl_xor_sync(0xffffffffu, sq, 1);
        sq += __shfl_xor_sync(0xffffffffu, sq, 2);
        float mu = s * (1.f / 128.f);
        float rstd = rsqrtf(sq * (1.f / 128.f) - mu * mu + 1e-5f);
#pragma unroll
        for (int u = 0; u < 8; u++) {
            int cb = jq * 32 + u * 4;
            float4 w4 = *(const float4*)&ffn_norm_w[g * 128 + cb];
            float4 b4 = *(const float4*)&ffn_norm_b[g * 128 + cb];
            float4 g4 = *(const float4*)&hs[tok * 132 + cb];
            float4 h4;
            h4.x = ((xv[u].x - mu) * rstd * w4.x + b4.x) * g4.x;
            h4.y = ((xv[u].y - mu) * rstd * w4.y + b4.y) * g4.y;
            h4.z = ((xv[u].z - mu) * rstd * w4.z + b4.z) * g4.z;
            h4.w = ((xv[u].w - mu) * rstd * w4.w + b4.w) * g4.w;
            *(float4*)&hs[tok * 132 + cb] = h4;
        }
    }
    __syncthreads();

    // ================= FFN =================
    float d0[4][4], d1[4][4];
    fz(d0); fz(d1);
    for (int ch = 0; ch < 8; ch++) {
        fz(c);
        gemm_tile(hs, 132, ffn_up_w + (size_t)g * 128 * 512 + ch * 64, 512, 128, wsm, c, ty, tx, tid);
#pragma unroll
        for (int tt = 0; tt < 4; tt++)
#pragma unroll
            for (int j = 0; j < 4; j++) {
                float u = c[tt][j] + ffn_up_b[g * 512 + ch * 64 + tx * 4 + j];
                bB[(ty * 4 + tt) * 68 + tx * 4 + j] = 0.5f * u * (1.f + erff(u * 0.70710678f));
            }
        gemm_tile(bB, 68, ffn_down_w + (size_t)g * 512 * 128 + (size_t)ch * 64 * 128, 128, 64, wsm, d0, ty, tx, tid);
        gemm_tile(bB, 68, ffn_down_w + (size_t)g * 512 * 128 + (size_t)ch * 64 * 128 + 64, 128, 64, wsm, d1, ty, tx, tid);
    }

    // ================= x_out =================
#pragma unroll
    for (int tt = 0; tt < 4; tt++) {
        int t = ty * 4 + tt;
        size_t tg = t0 + t;
        float4 v0, v1;
        int o0 = tx * 4, o1 = 64 + tx * 4;
        v0.x = xs[t * 132 + o0 + 0] + d0[tt][0] + ffn_down_b[g * 128 + o0 + 0];
        v0.y = xs[t * 132 + o0 + 1] + d0[tt][1] + ffn_down_b[g * 128 + o0 + 1];
        v0.z = xs[t * 132 + o0 + 2] + d0[tt][2] + ffn_down_b[g * 128 + o0 + 2];
        v0.w = xs[t * 132 + o0 + 3] + d0[tt][3] + ffn_down_b[g * 128 + o0 + 3];
        v1.x = xs[t * 132 + o1 + 0] + d1[tt][0] + ffn_down_b[g * 128 + o1 + 0];
        v1.y = xs[t * 132 + o1 + 1] + d1[tt][1] + ffn_down_b[g * 128 + o1 + 1];
        v1.z = xs[t * 132 + o1 + 2] + d1[tt][2] + ffn_down_b[g * 128 + o1 + 2];
        v1.w = xs[t * 132 + o1 + 3] + d1[tt][3] + ffn_down_b[g * 128 + o1 + 3];
        *(float4*)&xs[t * 132 + o0] = v0;
        *(float4*)&xs[t * 132 + o1] = v1;
        *(float4*)&out[O_XOUT + (tg * Gn + g) * 128 + o0] = v0;
        *(float4*)&out[O_XOUT + (tg * Gn + g) * 128 + o1] = v1;
    }
    __syncthreads();

    // ================= z_hat =================
    fz(c);
    gemm_tile(bA, 68, pred_w + (size_t)g * 64 * 64, 64, 64, wsm, c, ty, tx, tid);
#pragma unroll
    for (int tt = 0; tt < 4; tt++) {
        size_t tg = t0 + ty * 4 + tt;
        float4 v;
        v.x = c[tt][0] + pred_b[g * 64 + tx * 4 + 0];
        v.y = c[tt][1] + pred_b[g * 64 + tx * 4 + 1];
        v.z = c[tt][2] + pred_b[g * 64 + tx * 4 + 2];
        v.w = c[tt][3] + pred_b[g * 64 + tx * 4 + 3];
        *(float4*)&out[O_ZHAT + (tg * Gn + g) * 64 + tx * 4] = v;
    }

    // ================= post projection (4 x 64 chunks) =================
    for (int ch = 0; ch < 4; ch++) {
        fz(c);
        gemm_tile(xs, 132, post_w + (size_t)g * 128 * 257 + ch * 64, 257, 128, wsm, c, ty, tx, tid);
        if (ch == 1 || ch == 3) {
            long long off = (ch == 1) ? O_VP : O_VC;
#pragma unroll
            for (int tt = 0; tt < 4; tt++) {
                size_t tg = t0 + ty * 4 + tt;
                float4 v;
                v.x = c[tt][0] + post_b[g * 257 + ch * 64 + tx * 4 + 0];
                v.y = c[tt][1] + post_b[g * 257 + ch * 64 + tx * 4 + 1];
                v.z = c[tt][2] + post_b[g * 257 + ch * 64 + tx * 4 + 2];
                v.w = c[tt][3] + post_b[g * 257 + ch * 64 + tx * 4 + 3];
                *(float4*)&out[off + (tg * Gn + g) * 64 + tx * 4] = v;
            }
        } else {
#pragma unroll
            for (int tt = 0; tt < 4; tt++)
#pragma unroll
                for (int j = 0; j < 4; j++)
                    bB[(ty * 4 + tt) * 68 + tx * 4 + j] =
                        c[tt][j] + post_b[g * 257 + ch * 64 + tx * 4 + j];
            __syncthreads();
            long long off = (ch == 0) ? O_KC : O_QN;
            float4 r4[4];
            float ss = 0.f;
#pragma unroll
            for (int u4 = 0; u4 < 4; u4++) {
                r4[u4] = *(const float4*)&bB[tok * 68 + jq * 16 + u4 * 4];
                ss += r4[u4].x * r4[u4].x + r4[u4].y * r4[u4].y
                    + r4[u4].z * r4[u4].z + r4[u4].w * r4[u4].w;
            }
            ss += __shfl_xor_sync(0xffffffffu, ss, 1);
            ss += __shfl_xor_sync(0xffffffffu, ss, 2);
            float inv = 1.f / (sqrtf(ss) + 1e-6f);
            size_t tg = t0 + tok;
#pragma unroll
            for (int u4 = 0; u4 < 4; u4++) {
                float4 v;
                v.x = r4[u4].x * inv; v.y = r4[u4].y * inv;
                v.z = r4[u4].z * inv; v.w = r4[u4].w * inv;
                *(float4*)&out[off + (tg * Gn + g) * 64 + jq * 16 + u4 * 4] = v;
            }
            __syncthreads();
        }
    }

    // ================= w_nov (proj column 256) =================
    __syncthreads();
    if (tid < 128)
        wsm[tid] = post_w[(size_t)g * 128 * 257 + (size_t)tid * 257 + 256];
    __syncthreads();
    {
        float acc = 0.f;
#pragma unroll
        for (int u = 0; u < 8; u++) {
            float4 xv = *(const float4*)&xs[tok * 132 + jq * 32 + u * 4];
            float4 wv = *(const float4*)&wsm[jq * 32 + u * 4];
            acc += xv.x * wv.x + xv.y * wv.y + xv.z * wv.z + xv.w * wv.w;
        }
        acc += __shfl_xor_sync(0xffffffffu, acc, 1);
        acc += __shfl_xor_sync(0xffffffffu, acc, 2);
        if (jq == 0) {
            size_t tg = t0 + tok;
            float nv = acc + post_b[g * 257 + 256];
            out[O_WN + tg * Gn + g] = 1.f / (1.f + expf(-nv));
        }
    }
}

extern "C" void kernel_launch(void* const* d_in, const int* in_sizes, int n_in,
                              void* d_out, int out_size) {
    const float* x_col      = (const float*)d_in[0];
    const float* pm_state   = (const float*)d_in[1];
    const float* em_state   = (const float*)d_in[2];
    const float* z_hat_prev = (const float*)d_in[3];
    const float* ffn_norm_w = (const float*)d_in[4];
    const float* ffn_norm_b = (const float*)d_in[5];
    const float* ffn_up_w   = (const float*)d_in[6];
    const float* ffn_up_b   = (const float*)d_in[7];
    const float* ffn_down_w = (const float*)d_in[8];
    const float* ffn_down_b = (const float*)d_in[9];
    const float* pm_up_w    = (const float*)d_in[10];
    const float* pm_up_b    = (const float*)d_in[11];
    const float* pm_down_w  = (const float*)d_in[12];
    const float* pm_down_b  = (const float*)d_in[13];
    const float* em_up_w    = (const float*)d_in[14];
    const float* em_up_b    = (const float*)d_in[15];
    const float* em_down_w  = (const float*)d_in[16];
    const float* em_down_b  = (const float*)d_in[17];
    const float* post_w     = (const float*)d_in[18];
    const float* post_b     = (const float*)d_in[19];
    const float* enc_w      = (const float*)d_in[20];
    const float* enc_b      = (const float*)d_in[21];
    const float* pred_w     = (const float*)d_in[22];
    const float* pred_b     = (const float*)d_in[23];
    const float* gain_w     = (const float*)d_in[24];
    const float* gain_b     = (const float*)d_in[25];
    float* out = (float*)d_out;

    const int smem = (64 * 132 * 2 + 64 * 68 * 2 + 16 * 68) * 4;  // 106752 B
    cudaFuncSetAttribute(ccg_kernel, cudaFuncAttributeMaxDynamicSharedMemorySize, smem);
    dim3 grid(32, 128);
    ccg_kernel<<<grid, 256, smem>>>(
        x_col, pm_state, em_state, z_hat_prev,
        ffn_norm_w, ffn_norm_b, ffn_up_w, ffn_up_b, ffn_down_w, ffn_down_b,
        pm_up_w, pm_up_b, pm_down_w, pm_down_b,
        em_up_w, em_up_b, em_down_w, em_down_b,
        post_w, post_b, enc_w, enc_b, pred_w, pred_b, gain_w, gain_b,
        out);
}

// round 3
// speedup vs baseline: 1.1188x; 1.1188x over previous
#include <cuda_runtime.h>
#include <math.h>

#define Gn 128
typedef unsigned long long U64;

static const long long O_XOUT = 0LL;
static const long long O_Z    = 33554432LL;
static const long long O_ZHAT = 50331648LL;
static const long long O_SURP = 67108864LL;
static const long long O_KC   = 67371008LL;
static const long long O_VP   = 84148224LL;
static const long long O_GATE = 100925440LL;
static const long long O_QN   = 101187584LL;
static const long long O_VC   = 117964800LL;
static const long long O_WN   = 134742016LL;
static const long long O_S4   = 135004160LL;

__device__ __forceinline__ void f2fma(U64& d, U64 a, U64 b) {
    asm("fma.rn.f32x2 %0, %1, %2, %0;" : "+l"(d) : "l"(a), "l"(b));
}
__device__ __forceinline__ U64 dup2(float a) {
    U64 r; asm("mov.b64 %0, {%1, %1};" : "=l"(r) : "f"(a)); return r;
}
__device__ __forceinline__ float2 unpk(U64 v) {
    float2 f; asm("mov.b64 {%0, %1}, %2;" : "=f"(f.x), "=f"(f.y) : "l"(v)); return f;
}
__device__ __forceinline__ void cpa16(float* dst, const float* src) {
    unsigned d = (unsigned)__cvta_generic_to_shared(dst);
    asm volatile("cp.async.ca.shared.global [%0], [%1], 16;" :: "r"(d), "l"(src) : "memory");
}
__device__ __forceinline__ void cpa4(float* dst, const float* src) {
    unsigned d = (unsigned)__cvta_generic_to_shared(dst);
    asm volatile("cp.async.ca.shared.global [%0], [%1], 4;" :: "r"(d), "l"(src) : "memory");
}
__device__ __forceinline__ void cpcommit() { asm volatile("cp.async.commit_group;" ::: "memory"); }
__device__ __forceinline__ void cpwait0()  { asm volatile("cp.async.wait_group 0;" ::: "memory"); }

// ---------- staging ----------
__device__ __forceinline__ void st64(const float* __restrict__ W, long wst, int k0,
                                     float* buf, int tid) {
    int r = tid >> 4, cc = tid & 15;
    cpa16(&buf[r * 68 + cc * 4], &W[(size_t)(k0 + r) * wst + cc * 4]);
    cpcommit();
}
__device__ __forceinline__ void st128(const float* __restrict__ W, long wst, int k0,
                                      float* buf, int tid) {
    int r = tid >> 4, cc = tid & 15;
    const float* s = &W[(size_t)(k0 + r) * wst + cc * 4];
    cpa16(&buf[r * 136 + cc * 4], s);
    cpa16(&buf[r * 136 + 68 + cc * 4], s + 64);
    cpcommit();
}
__device__ __forceinline__ void st128u(const float* __restrict__ W, long wst, int k0,
                                       float* buf, int tid) {  // 4B-aligned src (post_w)
#pragma unroll
    for (int j = 0; j < 8; j++) {
        int flat = tid + 256 * j;
        int r = flat >> 7, col = flat & 127;
        cpa4(&buf[r * 136 + col + ((col >> 6) << 2)], &W[(size_t)(k0 + r) * wst + col]);
    }
    cpcommit();
}

// ---------- GEMM cores (f32x2). c2[tt][p] = cols (base + tx*4 + 2p, +2p+1) ----------
__device__ __forceinline__ void inner64(const float* __restrict__ As, int sas, int k0,
                                        const float* wb, U64 c2[][2], int ty, int tx) {
#pragma unroll
    for (int i4 = 0; i4 < 4; i4++) {
        float4 a4[4];
#pragma unroll
        for (int tt = 0; tt < 4; tt++)
            a4[tt] = *(const float4*)&As[(ty * 4 + tt) * sas + k0 + i4 * 4];
#pragma unroll
        for (int ii = 0; ii < 4; ii++) {
            ulonglong2 w = *(const ulonglong2*)&wb[(i4 * 4 + ii) * 68 + tx * 4];
#pragma unroll
            for (int tt = 0; tt < 4; tt++) {
                U64 a = dup2(((const float*)&a4[tt])[ii]);
                f2fma(c2[tt][0], a, w.x);
                f2fma(c2[tt][1], a, w.y);
            }
        }
    }
}

__device__ __forceinline__ void gemm64(const float* __restrict__ As, int sas,
                                       const float* __restrict__ W, long wst, int K,
                                       float* wsm, U64 c2[][2], int ty, int tx, int tid) {
    int nc = K >> 4;
    st64(W, wst, 0, wsm, tid);
    for (int c = 0; c < nc; c++) {
        cpwait0();
        __syncthreads();
        if (c + 1 < nc) st64(W, wst, (c + 1) << 4, wsm + ((c + 1) & 1) * 1088, tid);
        inner64(As, sas, c << 4, wsm + (c & 1) * 1088, c2, ty, tx);
    }
    __syncthreads();
}

// transposed-B staging (attention logits): W[k][s] = S[s][k]
__device__ __forceinline__ void gemm64T(const float* __restrict__ As, int sas,
                                        const float* __restrict__ S, int slots, int K,
                                        float* wsm, U64 c2[][2], int ty, int tx, int tid) {
    for (int k0 = 0; k0 < K; k0 += 16) {
        int s = tid & 63, k4 = tid >> 6;
        float4 v = make_float4(0.f, 0.f, 0.f, 0.f);
        if (s < slots) v = *(const float4*)&S[s * 64 + k0 + k4 * 4];
        __syncthreads();
        wsm[(k4 * 4 + 0) * 68 + s] = v.x;
        wsm[(k4 * 4 + 1) * 68 + s] = v.y;
        wsm[(k4 * 4 + 2) * 68 + s] = v.z;
        wsm[(k4 * 4 + 3) * 68 + s] = v.w;
        __syncthreads();
        inner64(As, sas, k0, wsm, c2, ty, tx);
    }
    __syncthreads();
}

__device__ __forceinline__ void inner128(const float* __restrict__ As, int sas, int k0,
                                         const float* wb, U64 c2[][4], int ty, int tx) {
#pragma unroll
    for (int i4 = 0; i4 < 4; i4++) {
        float4 a4[4];
#pragma unroll
        for (int tt = 0; tt < 4; tt++)
            a4[tt] = *(const float4*)&As[(ty * 4 + tt) * sas + k0 + i4 * 4];
#pragma unroll
        for (int ii = 0; ii < 4; ii++) {
            ulonglong2 w0 = *(const ulonglong2*)&wb[(i4 * 4 + ii) * 136 + tx * 4];
            ulonglong2 w1 = *(const ulonglong2*)&wb[(i4 * 4 + ii) * 136 + 68 + tx * 4];
#pragma unroll
            for (int tt = 0; tt < 4; tt++) {
                U64 a = dup2(((const float*)&a4[tt])[ii]);
                f2fma(c2[tt][0], a, w0.x);
                f2fma(c2[tt][1], a, w0.y);
                f2fma(c2[tt][2], a, w1.x);
                f2fma(c2[tt][3], a, w1.y);
            }
        }
    }
}

__device__ __forceinline__ void gemm128(const float* __restrict__ As, int sas,
                                        const float* __restrict__ W, long wst, int K,
                                        float* wsm, U64 c2[][4], int ty, int tx, int tid) {
    int nc = K >> 4;
    st128(W, wst, 0, wsm, tid);
    for (int c = 0; c < nc; c++) {
        cpwait0();
        __syncthreads();
        if (c + 1 < nc) st128(W, wst, (c + 1) << 4, wsm + ((c + 1) & 1) * 2176, tid);
        inner128(As, sas, c << 4, wsm + (c & 1) * 2176, c2, ty, tx);
    }
    __syncthreads();
}

__device__ __forceinline__ void gemm128u(const float* __restrict__ As, int sas,
                                         const float* __restrict__ W, long wst, int K,
                                         float* wsm, U64 c2[][4], int ty, int tx, int tid) {
    int nc = K >> 4;
    st128u(W, wst, 0, wsm, tid);
    for (int c = 0; c < nc; c++) {
        cpwait0();
        __syncthreads();
        if (c + 1 < nc) st128u(W, wst, (c + 1) << 4, wsm + ((c + 1) & 1) * 2176, tid);
        inner128(As, sas, c << 4, wsm + (c & 1) * 2176, c2, ty, tx);
    }
    __syncthreads();
}

__device__ __forceinline__ void fz2(U64* c, int n) {
    for (int i = 0; i < n; i++) c[i] = 0ULL;
}
__device__ __forceinline__ void up2(const U64* c2, float* o) {  // 2 pairs -> 4 floats
    float2 a = unpk(c2[0]), b = unpk(c2[1]);
    o[0] = a.x; o[1] = a.y; o[2] = b.x; o[3] = b.y;
}

template <int SLOTS>
__device__ __forceinline__ void softmax_q(float* buf, int tok, int jq) {
    const int nS = SLOTS / 4;
    float l[nS];
    float m = -1e30f;
#pragma unroll
    for (int i = 0; i < nS; i++) {
        l[i] = buf[tok * 68 + jq * nS + i] * 0.125f;
        m = fmaxf(m, l[i]);
    }
    m = fmaxf(m, __shfl_xor_sync(0xffffffffu, m, 1));
    m = fmaxf(m, __shfl_xor_sync(0xffffffffu, m, 2));
    float s = 0.f;
#pragma unroll
    for (int i = 0; i < nS; i++) { l[i] = expf(l[i] - m); s += l[i]; }
    s += __shfl_xor_sync(0xffffffffu, s, 1);
    s += __shfl_xor_sync(0xffffffffu, s, 2);
    float inv = 1.f / s;
#pragma unroll
    for (int i = 0; i < nS; i++) buf[tok * 68 + jq * nS + i] = l[i] * inv;
}

__global__ void __launch_bounds__(256)
ccg_kernel(
    const float* __restrict__ x_col, const float* __restrict__ pm_state,
    const float* __restrict__ em_state, const float* __restrict__ z_hat_prev,
    const float* __restrict__ ffn_norm_w, const float* __restrict__ ffn_norm_b,
    const float* __restrict__ ffn_up_w, const float* __restrict__ ffn_up_b,
    const float* __restrict__ ffn_down_w, const float* __restrict__ ffn_down_b,
    const float* __restrict__ pm_up_w, const float* __restrict__ pm_up_b,
    const float* __restrict__ pm_down_w, const float* __restrict__ pm_down_b,
    const float* __restrict__ em_up_w, const float* __restrict__ em_up_b,
    const float* __restrict__ em_down_w, const float* __restrict__ em_down_b,
    const float* __restrict__ post_w, const float* __restrict__ post_b,
    const float* __restrict__ enc_w, const float* __restrict__ enc_b,
    const float* __restrict__ pred_w, const float* __restrict__ pred_b,
    const float* __restrict__ gain_w, const float* __restrict__ gain_b,
    float* __restrict__ out)
{
    extern __shared__ float smf[];
    float* xs   = smf;                 // 64 x 132
    float* hs   = xs + 64 * 132;       // 64 x 132
    float* gbuf = hs + 64 * 132;       // 64 x 132
    float* bA   = gbuf + 64 * 132;     // 64 x 68
    float* bB   = bA + 64 * 68;        // 64 x 68
    float* wsm  = bB + 64 * 68;        // 2 x 2176

    const int tid = threadIdx.x;
    const int ty = tid >> 4, tx = tid & 15;
    const int tok = tid >> 2, jq = tid & 3;
    const int g  = blockIdx.y;
    const int t0 = blockIdx.x * 64;
    const int bs = t0 >> 9;
    const int bidx = g >> 4;

    // ---- load x tile ----
#pragma unroll
    for (int jj = 0; jj < 8; jj++) {
        int flat = tid + 256 * jj;
        int r = flat >> 5, c4 = flat & 31;
        *(float4*)&xs[r * 132 + c4 * 4] =
            *(const float4*)&x_col[((size_t)(t0 + r) * Gn + g) * 128 + c4 * 4];
    }

    // ================= pm memory stage =================
    {
        U64 c2[4][2]; fz2(&c2[0][0], 8);
        gemm64(xs, 132, pm_up_w + (size_t)g * 8192, 64, 128, wsm, c2, ty, tx, tid);
#pragma unroll
        for (int tt = 0; tt < 4; tt++) {
            float o[4]; up2(c2[tt], o);
#pragma unroll
            for (int j = 0; j < 4; j++)
                bB[(ty * 4 + tt) * 68 + tx * 4 + j] = o[j] + pm_up_b[g * 64 + tx * 4 + j];
        }
    }
    const float* Spm = pm_state + (size_t)((bs * 8 + bidx) * 16) * 64;
    {
        U64 c2[4][2]; fz2(&c2[0][0], 8);
        gemm64T(bB, 68, Spm, 16, 64, wsm, c2, ty, tx, tid);
        if (tx < 4) {
#pragma unroll
            for (int tt = 0; tt < 4; tt++) {
                float o[4]; up2(c2[tt], o);
#pragma unroll
                for (int j = 0; j < 4; j++) bA[(ty * 4 + tt) * 68 + tx * 4 + j] = o[j];
            }
        }
    }
    __syncthreads();
    softmax_q<16>(bA, tok, jq);
    __syncthreads();
    {
        U64 c2[4][2]; fz2(&c2[0][0], 8);
        gemm64(bA, 68, Spm, 64, 16, wsm, c2, ty, tx, tid);
#pragma unroll
        for (int tt = 0; tt < 4; tt++) {
            float o[4]; up2(c2[tt], o);
#pragma unroll
            for (int j = 0; j < 4; j++) bB[(ty * 4 + tt) * 68 + tx * 4 + j] = o[j];
        }
    }
    {
        U64 c2[4][4]; fz2(&c2[0][0], 16);
        gemm128(bB, 68, pm_down_w + (size_t)g * 8192, 128, 64, wsm, c2, ty, tx, tid);
#pragma unroll
        for (int tt = 0; tt < 4; tt++) {
            float o0[4], o1[4]; up2(&c2[tt][0], o0); up2(&c2[tt][2], o1);
#pragma unroll
            for (int j = 0; j < 4; j++) {
                int a = tx * 4 + j, b = 64 + tx * 4 + j;
                xs[(ty * 4 + tt) * 132 + a] += o0[j] + pm_down_b[g * 128 + a];
                xs[(ty * 4 + tt) * 132 + b] += o1[j] + pm_down_b[g * 128 + b];
            }
        }
    }

    // ================= em memory stage =================
    {
        U64 c2[4][2]; fz2(&c2[0][0], 8);
        gemm64(xs, 132, em_up_w + (size_t)g * 8192, 64, 128, wsm, c2, ty, tx, tid);
#pragma unroll
        for (int tt = 0; tt < 4; tt++) {
            float o[4]; up2(c2[tt], o);
#pragma unroll
            for (int j = 0; j < 4; j++)
                bB[(ty * 4 + tt) * 68 + tx * 4 + j] = o[j] + em_up_b[g * 64 + tx * 4 + j];
        }
    }
    const float* Sem = em_state + (size_t)((bs * 8 + bidx) * 64) * 64;
    {
        U64 c2[4][2]; fz2(&c2[0][0], 8);
        gemm64T(bB, 68, Sem, 64, 64, wsm, c2, ty, tx, tid);
#pragma unroll
        for (int tt = 0; tt < 4; tt++) {
            float o[4]; up2(c2[tt], o);
#pragma unroll
            for (int j = 0; j < 4; j++) bA[(ty * 4 + tt) * 68 + tx * 4 + j] = o[j];
        }
    }
    __syncthreads();
    softmax_q<64>(bA, tok, jq);
    __syncthreads();
    {
        U64 c2[4][2]; fz2(&c2[0][0], 8);
        gemm64(bA, 68, Sem, 64, 64, wsm, c2, ty, tx, tid);
#pragma unroll
        for (int tt = 0; tt < 4; tt++) {
            float o[4]; up2(c2[tt], o);
#pragma unroll
            for (int j = 0; j < 4; j++) bB[(ty * 4 + tt) * 68 + tx * 4 + j] = o[j];
        }
    }
    {
        U64 c2[4][4]; fz2(&c2[0][0], 16);
        gemm128(bB, 68, em_down_w + (size_t)g * 8192, 128, 64, wsm, c2, ty, tx, tid);
#pragma unroll
        for (int tt = 0; tt < 4; tt++) {
            float o0[4], o1[4]; up2(&c2[tt][0], o0); up2(&c2[tt][2], o1);
#pragma unroll
            for (int j = 0; j < 4; j++) {
                int a = tx * 4 + j, b = 64 + tx * 4 + j;
                xs[(ty * 4 + tt) * 132 + a] += o0[j] + em_down_b[g * 128 + a];
                xs[(ty * 4 + tt) * 132 + b] += o1[j] + em_down_b[g * 128 + b];
            }
        }
    }

    // ================= enc / delta / surprise =================
    {
        U64 c2[4][2]; fz2(&c2[0][0], 8);
        gemm64(xs, 132, enc_w + (size_t)g * 8192, 64, 128, wsm, c2, ty, tx, tid);
        float sp[4];
#pragma unroll
        for (int tt = 0; tt < 4; tt++) {
            int t = ty * 4 + tt;
            size_t tg = t0 + t;
            float o[4]; up2(c2[tt], o);
            float4 zh4 = *(const float4*)&z_hat_prev[(tg * Gn + g) * 64 + tx * 4];
            float z0 = o[0] + enc_b[g * 64 + tx * 4 + 0];
            float z1 = o[1] + enc_b[g * 64 + tx * 4 + 1];
            float z2 = o[2] + enc_b[g * 64 + tx * 4 + 2];
            float z3 = o[3] + enc_b[g * 64 + tx * 4 + 3];
            bA[t * 68 + tx * 4 + 0] = z0; bA[t * 68 + tx * 4 + 1] = z1;
            bA[t * 68 + tx * 4 + 2] = z2; bA[t * 68 + tx * 4 + 3] = z3;
            float e0 = z0 - zh4.x, e1 = z1 - zh4.y, e2 = z2 - zh4.z, e3 = z3 - zh4.w;
            bB[t * 68 + tx * 4 + 0] = e0; bB[t * 68 + tx * 4 + 1] = e1;
            bB[t * 68 + tx * 4 + 2] = e2; bB[t * 68 + tx * 4 + 3] = e3;
            sp[tt] = e0 * e0 + e1 * e1 + e2 * e2 + e3 * e3;
            *(float4*)&out[O_Z + (tg * Gn + g) * 64 + tx * 4] = make_float4(z0, z1, z2, z3);
        }
#pragma unroll
        for (int tt = 0; tt < 4; tt++) {
            sp[tt] += __shfl_xor_sync(0xffffffffu, sp[tt], 1);
            sp[tt] += __shfl_xor_sync(0xffffffffu, sp[tt], 2);
            sp[tt] += __shfl_xor_sync(0xffffffffu, sp[tt], 4);
            sp[tt] += __shfl_xor_sync(0xffffffffu, sp[tt], 8);
        }
        if (tx == 0) {
#pragma unroll
            for (int tt = 0; tt < 4; tt++) {
                size_t tg = t0 + ty * 4 + tt;
                float s = sqrtf(sp[tt]);
                out[O_SURP + tg * Gn + g] = s;
                out[O_S4 + tg * Gn + g] = s;
                out[O_GATE + tg * Gn + g] = fminf(s, 1.f);
            }
        }
    }

    // ================= gain =================
    {
        U64 c2[4][4]; fz2(&c2[0][0], 16);
        gemm128(bB, 68, gain_w + (size_t)g * 8192, 128, 64, wsm, c2, ty, tx, tid);
#pragma unroll
        for (int tt = 0; tt < 4; tt++) {
            float o0[4], o1[4]; up2(&c2[tt][0], o0); up2(&c2[tt][2], o1);
#pragma unroll
            for (int j = 0; j < 4; j++) {
                int a = tx * 4 + j, b = 64 + tx * 4 + j;
                hs[(ty * 4 + tt) * 132 + a] = 1.f + 0.1f * tanhf(o0[j] + gain_b[g * 128 + a]);
                hs[(ty * 4 + tt) * 132 + b] = 1.f + 0.1f * tanhf(o1[j] + gain_b[g * 128 + b]);
            }
        }
    }
    __syncthreads();

    // ================= layernorm * gain -> hs =================
    {
        float s = 0.f, sq = 0.f;
        float4 xv[8];
#pragma unroll
        for (int u = 0; u < 8; u++) {
            xv[u] = *(const float4*)&xs[tok * 132 + jq * 32 + u * 4];
            s  += xv[u].x + xv[u].y + xv[u].z + xv[u].w;
            sq += xv[u].x * xv[u].x + xv[u].y * xv[u].y + xv[u].z * xv[u].z + xv[u].w * xv[u].w;
        }
        s  += __shfl_xor_sync(0xffffffffu, s, 1);
        s  += __shfl_xor_sync(0xffffffffu, s, 2);
        sq += __shfl_xor_sync(0xffffffffu, sq, 1);
        sq += __shfl_xor_sync(0xffffffffu, sq, 2);
        float mu = s * (1.f / 128.f);
        float rstd = rsqrtf(sq * (1.f / 128.f) - mu * mu + 1e-5f);
#pragma unroll
        for (int u = 0; u < 8; u++) {
            int cb = jq * 32 + u * 4;
            float4 w4 = *(const float4*)&ffn_norm_w[g * 128 + cb];
            float4 b4 = *(const float4*)&ffn_norm_b[g * 128 + cb];
            float4 g4 = *(const float4*)&hs[tok * 132 + cb];
            float4 h4;
            h4.x = ((xv[u].x - mu) * rstd * w4.x + b4.x) * g4.x;
            h4.y = ((xv[u].y - mu) * rstd * w4.y + b4.y) * g4.y;
            h4.z = ((xv[u].z - mu) * rstd * w4.z + b4.z) * g4.z;
            h4.w = ((xv[u].w - mu) * rstd * w4.w + b4.w) * g4.w;
            *(float4*)&hs[tok * 132 + cb] = h4;
        }
    }

    // ================= FFN =================
    U64 d2[4][4]; fz2(&d2[0][0], 16);
    for (int ch = 0; ch < 4; ch++) {
        {
            U64 c2[4][4]; fz2(&c2[0][0], 16);
            gemm128(hs, 132, ffn_up_w + (size_t)g * 65536 + ch * 128, 512, 128, wsm, c2, ty, tx, tid);
#pragma unroll
            for (int tt = 0; tt < 4; tt++) {
                float o0[4], o1[4]; up2(&c2[tt][0], o0); up2(&c2[tt][2], o1);
#pragma unroll
                for (int j = 0; j < 4; j++) {
                    float u0 = o0[j] + ffn_up_b[g * 512 + ch * 128 + tx * 4 + j];
                    float u1 = o1[j] + ffn_up_b[g * 512 + ch * 128 + 64 + tx * 4 + j];
                    gbuf[(ty * 4 + tt) * 132 + tx * 4 + j]      = 0.5f * u0 * (1.f + erff(u0 * 0.70710678f));
                    gbuf[(ty * 4 + tt) * 132 + 64 + tx * 4 + j] = 0.5f * u1 * (1.f + erff(u1 * 0.70710678f));
                }
            }
        }
        gemm128(gbuf, 132, ffn_down_w + (size_t)g * 65536 + (size_t)ch * 128 * 128, 128, 128, wsm, d2, ty, tx, tid);
    }

    // ================= x_out =================
#pragma unroll
    for (int tt = 0; tt < 4; tt++) {
        int t = ty * 4 + tt;
        size_t tg = t0 + t;
        float o0[4], o1[4]; up2(&d2[tt][0], o0); up2(&d2[tt][2], o1);
        float4 v0, v1;
        int a = tx * 4, b = 64 + tx * 4;
        v0.x = xs[t * 132 + a + 0] + o0[0] + ffn_down_b[g * 128 + a + 0];
        v0.y = xs[t * 132 + a + 1] + o0[1] + ffn_down_b[g * 128 + a + 1];
        v0.z = xs[t * 132 + a + 2] + o0[2] + ffn_down_b[g * 128 + a + 2];
        v0.w = xs[t * 132 + a + 3] + o0[3] + ffn_down_b[g * 128 + a + 3];
        v1.x = xs[t * 132 + b + 0] + o1[0] + ffn_down_b[g * 128 + b + 0];
        v1.y = xs[t * 132 + b + 1] + o1[1] + ffn_down_b[g * 128 + b + 1];
        v1.z = xs[t * 132 + b + 2] + o1[2] + ffn_down_b[g * 128 + b + 2];
        v1.w = xs[t * 132 + b + 3] + o1[3] + ffn_down_b[g * 128 + b + 3];
        *(float4*)&xs[t * 132 + a] = v0;
        *(float4*)&xs[t * 132 + b] = v1;
        *(float4*)&out[O_XOUT + (tg * Gn + g) * 128 + a] = v0;
        *(float4*)&out[O_XOUT + (tg * Gn + g) * 128 + b] = v1;
    }

    // ================= z_hat =================
    {
        U64 c2[4][2]; fz2(&c2[0][0], 8);
        gemm64(bA, 68, pred_w + (size_t)g * 4096, 64, 64, wsm, c2, ty, tx, tid);
#pragma unroll
        for (int tt = 0; tt < 4; tt++) {
            size_t tg = t0 + ty * 4 + tt;
            float o[4]; up2(c2[tt], o);
            float4 v;
            v.x = o[0] + pred_b[g * 64 + tx * 4 + 0];
            v.y = o[1] + pred_b[g * 64 + tx * 4 + 1];
            v.z = o[2] + pred_b[g * 64 + tx * 4 + 2];
            v.w = o[3] + pred_b[g * 64 + tx * 4 + 3];
            *(float4*)&out[O_ZHAT + (tg * Gn + g) * 64 + tx * 4] = v;
        }
    }

    // ================= post projection: two 128-wide passes =================
    for (int ph = 0; ph < 2; ph++) {
        U64 c2[4][4]; fz2(&c2[0][0], 16);
        gemm128u(xs, 132, post_w + (size_t)g * 32896 + ph * 128, 257, 128, wsm, c2, ty, tx, tid);
        long long voff = ph ? O_VC : O_VP;
        long long noff = ph ? O_QN : O_KC;
#pragma unroll
        for (int tt = 0; tt < 4; tt++) {
            size_t tg = t0 + ty * 4 + tt;
            float o0[4], o1[4]; up2(&c2[tt][0], o0); up2(&c2[tt][2], o1);
            // first 64: goes to bB for normalization
#pragma unroll
            for (int j = 0; j < 4; j++)
                bB[(ty * 4 + tt) * 68 + tx * 4 + j] =
                    o0[j] + post_b[g * 257 + ph * 128 + tx * 4 + j];
            // second 64: direct store with bias
            float4 v;
            v.x = o1[0] + post_b[g * 257 + ph * 128 + 64 + tx * 4 + 0];
            v.y = o1[1] + post_b[g * 257 + ph * 128 + 64 + tx * 4 + 1];
            v.z = o1[2] + post_b[g * 257 + ph * 128 + 64 + tx * 4 + 2];
            v.w = o1[3] + post_b[g * 257 + ph * 128 + 64 + tx * 4 + 3];
            *(float4*)&out[voff + (tg * Gn + g) * 64 + tx * 4] = v;
        }
        __syncthreads();
        // normalize bB rows -> out[noff]
        {
            float4 r4[4];
            float ss = 0.f;
#pragma unroll
            for (int u4 = 0; u4 < 4; u4++) {
                r4[u4] = *(const float4*)&bB[tok * 68 + jq * 16 + u4 * 4];
                ss += r4[u4].x * r4[u4].x + r4[u4].y * r4[u4].y
                    + r4[u4].z * r4[u4].z + r4[u4].w * r4[u4].w;
            }
            ss += __shfl_xor_sync(0xffffffffu, ss, 1);
            ss += __shfl_xor_sync(0xffffffffu, ss, 2);
            float inv = 1.f / (sqrtf(ss) + 1e-6f);
            size_t tg = t0 + tok;
#pragma unroll
            for (int u4 = 0; u4 < 4; u4++) {
                float4 v;
                v.x = r4[u4].x * inv; v.y = r4[u4].y * inv;
                v.z = r4[u4].z * inv; v.w = r4[u4].w * inv;
                *(float4*)&out[noff + (tg * Gn + g) * 64 + jq * 16 + u4 * 4] = v;
            }
        }
        __syncthreads();
    }

    // ================= w_nov (proj column 256) =================
    if (tid < 128)
        wsm[tid] = post_w[(size_t)g * 32896 + (size_t)tid * 257 + 256];
    __syncthreads();
    {
        float acc = 0.f;
#pragma unroll
        for (int u = 0; u < 8; u++) {
            float4 xv = *(const float4*)&xs[tok * 132 + jq * 32 + u * 4];
            float4 wv = *(const float4*)&wsm[jq * 32 + u * 4];
            acc += xv.x * wv.x + xv.y * wv.y + xv.z * wv.z + xv.w * wv.w;
        }
        acc += __shfl_xor_sync(0xffffffffu, acc, 1);
        acc += __shfl_xor_sync(0xffffffffu, acc, 2);
        if (jq == 0) {
            size_t tg = t0 + tok;
            float nv = acc + post_b[g * 257 + 256];
            out[O_WN + tg * Gn + g] = 1.f / (1.f + expf(-nv));
        }
    }
}

extern "C" void kernel_launch(void* const* d_in, const int* in_sizes, int n_in,
                              void* d_out, int out_size) {
    const float* x_col      = (const float*)d_in[0];
    const float* pm_state   = (const float*)d_in[1];
    const float* em_state   = (const float*)d_in[2];
    const float* z_hat_prev = (const float*)d_in[3];
    const float* ffn_norm_w = (const float*)d_in[4];
    const float* ffn_norm_b = (const float*)d_in[5];
    const float* ffn_up_w   = (const float*)d_in[6];
    const float* ffn_up_b   = (const float*)d_in[7];
    const float* ffn_down_w = (const float*)d_in[8];
    const float* ffn_down_b = (const float*)d_in[9];
    const float* pm_up_w    = (const float*)d_in[10];
    const float* pm_up_b    = (const float*)d_in[11];
    const float* pm_down_w  = (const float*)d_in[12];
    const float* pm_down_b  = (const float*)d_in[13];
    const float* em_up_w    = (const float*)d_in[14];
    const float* em_up_b    = (const float*)d_in[15];
    const float* em_down_w  = (const float*)d_in[16];
    const float* em_down_b  = (const float*)d_in[17];
    const float* post_w     = (const float*)d_in[18];
    const float* post_b     = (const float*)d_in[19];
    const float* enc_w      = (const float*)d_in[20];
    const float* enc_b      = (const float*)d_in[21];
    const float* pred_w     = (const float*)d_in[22];
    const float* pred_b     = (const float*)d_in[23];
    const float* gain_w     = (const float*)d_in[24];
    const float* gain_b     = (const float*)d_in[25];
    float* out = (float*)d_out;

    const int smem = (64 * 132 * 3 + 64 * 68 * 2 + 2 * 2176) * 4;  // 153600 B
    cudaFuncSetAttribute(ccg_kernel, cudaFuncAttributeMaxDynamicSharedMemorySize, smem);
    dim3 grid(32, 128);
    ccg_kernel<<<grid, 256, smem>>>(
        x_col, pm_state, em_state, z_hat_prev,
        ffn_norm_w, ffn_norm_b, ffn_up_w, ffn_up_b, ffn_down_w, ffn_down_b,
        pm_up_w, pm_up_b, pm_down_w, pm_down_b,
        em_up_w, em_up_b, em_down_w, em_down_b,
        post_w, post_b, enc_w, enc_b, pred_w, pred_b, gain_w, gain_b,
        out);
}

// round 4
// speedup vs baseline: 1.2778x; 1.1422x over previous
#include <cuda_runtime.h>
#include <math.h>

#define Gn 128
typedef unsigned long long U64;

static const long long O_XOUT = 0LL;
static const long long O_Z    = 33554432LL;
static const long long O_ZHAT = 50331648LL;
static const long long O_SURP = 67108864LL;
static const long long O_KC   = 67371008LL;
static const long long O_VP   = 84148224LL;
static const long long O_GATE = 100925440LL;
static const long long O_QN   = 101187584LL;
static const long long O_VC   = 117964800LL;
static const long long O_WN   = 134742016LL;
static const long long O_S4   = 135004160LL;

__device__ __forceinline__ void f2fma(U64& d, U64 a, U64 b) {
    asm("fma.rn.f32x2 %0, %1, %2, %0;" : "+l"(d) : "l"(a), "l"(b));
}
__device__ __forceinline__ U64 dup2(float a) {
    U64 r; asm("mov.b64 %0, {%1, %1};" : "=l"(r) : "f"(a)); return r;
}
__device__ __forceinline__ float2 unpk(U64 v) {
    float2 f; asm("mov.b64 {%0, %1}, %2;" : "=f"(f.x), "=f"(f.y) : "l"(v)); return f;
}
__device__ __forceinline__ void cpa16(float* dst, const float* src) {
    unsigned d = (unsigned)__cvta_generic_to_shared(dst);
    asm volatile("cp.async.ca.shared.global [%0], [%1], 16;" :: "r"(d), "l"(src) : "memory");
}
__device__ __forceinline__ void cpa4(float* dst, const float* src) {
    unsigned d = (unsigned)__cvta_generic_to_shared(dst);
    asm volatile("cp.async.ca.shared.global [%0], [%1], 4;" :: "r"(d), "l"(src) : "memory");
}
__device__ __forceinline__ void cpcommit() { asm volatile("cp.async.commit_group;" ::: "memory"); }
__device__ __forceinline__ void cpwait0()  { asm volatile("cp.async.wait_group 0;" ::: "memory"); }

// ---------- staging ----------
// 16 k-rows x 64 cols -> buf stride 68
__device__ __forceinline__ void st64(const float* __restrict__ W, long wst, int k0,
                                     float* buf, int tid) {
    int r = tid >> 4, cc = tid & 15;
    cpa16(&buf[r * 68 + cc * 4], &W[(size_t)(k0 + r) * wst + cc * 4]);
    cpcommit();
}
// 8 k-rows x 128 cols -> buf stride 136 (two 68-halves)
__device__ __forceinline__ void st128(const float* __restrict__ W, long wst, int k0,
                                      float* buf, int tid) {
    int r = tid >> 5, c = tid & 31;
    int half = c >> 4, c4 = c & 15;
    cpa16(&buf[r * 136 + half * 68 + c4 * 4], &W[(size_t)(k0 + r) * wst + c * 4]);
    cpcommit();
}
// same, 4B-aligned source (post_w, stride 257)
__device__ __forceinline__ void st128u(const float* __restrict__ W, long wst, int k0,
                                       float* buf, int tid) {
#pragma unroll
    for (int j = 0; j < 4; j++) {
        int flat = tid + 256 * j;
        int r = flat >> 7, col = flat & 127;
        cpa4(&buf[r * 136 + col + ((col >> 6) << 2)], &W[(size_t)(k0 + r) * wst + col]);
    }
    cpcommit();
}

// ---------- GEMM cores (f32x2) ----------
__device__ __forceinline__ void inner64(const float* __restrict__ As, int sas, int k0,
                                        const float* wb, U64 c2[][2], int ty, int tx) {
#pragma unroll
    for (int i4 = 0; i4 < 4; i4++) {
        float4 a4[4];
#pragma unroll
        for (int tt = 0; tt < 4; tt++)
            a4[tt] = *(const float4*)&As[(ty * 4 + tt) * sas + k0 + i4 * 4];
#pragma unroll
        for (int ii = 0; ii < 4; ii++) {
            ulonglong2 w = *(const ulonglong2*)&wb[(i4 * 4 + ii) * 68 + tx * 4];
#pragma unroll
            for (int tt = 0; tt < 4; tt++) {
                U64 a = dup2(((const float*)&a4[tt])[ii]);
                f2fma(c2[tt][0], a, w.x);
                f2fma(c2[tt][1], a, w.y);
            }
        }
    }
}

__device__ __forceinline__ void gemm64(const float* __restrict__ As, int sas,
                                       const float* __restrict__ W, long wst, int K,
                                       float* wsm, U64 c2[][2], int ty, int tx, int tid) {
    int nc = K >> 4;
    st64(W, wst, 0, wsm, tid);
    for (int c = 0; c < nc; c++) {
        cpwait0();
        __syncthreads();
        if (c + 1 < nc) st64(W, wst, (c + 1) << 4, wsm + ((c + 1) & 1) * 1088, tid);
        inner64(As, sas, c << 4, wsm + (c & 1) * 1088, c2, ty, tx);
    }
    __syncthreads();
}

// transposed-B staging (attention logits): W[k][s] = S[s][k]
__device__ __forceinline__ void gemm64T(const float* __restrict__ As, int sas,
                                        const float* __restrict__ S, int slots, int K,
                                        float* wsm, U64 c2[][2], int ty, int tx, int tid) {
    for (int k0 = 0; k0 < K; k0 += 16) {
        int s = tid & 63, k4 = tid >> 6;
        float4 v = make_float4(0.f, 0.f, 0.f, 0.f);
        if (s < slots) v = *(const float4*)&S[s * 64 + k0 + k4 * 4];
        __syncthreads();
        wsm[(k4 * 4 + 0) * 68 + s] = v.x;
        wsm[(k4 * 4 + 1) * 68 + s] = v.y;
        wsm[(k4 * 4 + 2) * 68 + s] = v.z;
        wsm[(k4 * 4 + 3) * 68 + s] = v.w;
        __syncthreads();
        inner64(As, sas, k0, wsm, c2, ty, tx);
    }
    __syncthreads();
}

__device__ __forceinline__ void inner128(const float* __restrict__ As, int sas, int k0,
                                         const float* wb, U64 c2[][4], int ty, int tx) {
#pragma unroll
    for (int i4 = 0; i4 < 2; i4++) {
        float4 a4[4];
#pragma unroll
        for (int tt = 0; tt < 4; tt++)
            a4[tt] = *(const float4*)&As[(ty * 4 + tt) * sas + k0 + i4 * 4];
#pragma unroll
        for (int ii = 0; ii < 4; ii++) {
            ulonglong2 w0 = *(const ulonglong2*)&wb[(i4 * 4 + ii) * 136 + tx * 4];
            ulonglong2 w1 = *(const ulonglong2*)&wb[(i4 * 4 + ii) * 136 + 68 + tx * 4];
#pragma unroll
            for (int tt = 0; tt < 4; tt++) {
                U64 a = dup2(((const float*)&a4[tt])[ii]);
                f2fma(c2[tt][0], a, w0.x);
                f2fma(c2[tt][1], a, w0.y);
                f2fma(c2[tt][2], a, w1.x);
                f2fma(c2[tt][3], a, w1.y);
            }
        }
    }
}

__device__ __forceinline__ void gemm128(const float* __restrict__ As, int sas,
                                        const float* __restrict__ W, long wst, int K,
                                        float* wsm, U64 c2[][4], int ty, int tx, int tid) {
    int nc = K >> 3;
    st128(W, wst, 0, wsm, tid);
    for (int c = 0; c < nc; c++) {
        cpwait0();
        __syncthreads();
        if (c + 1 < nc) st128(W, wst, (c + 1) << 3, wsm + ((c + 1) & 1) * 1088, tid);
        inner128(As, sas, c << 3, wsm + (c & 1) * 1088, c2, ty, tx);
    }
    __syncthreads();
}

__device__ __forceinline__ void gemm128u(const float* __restrict__ As, int sas,
                                         const float* __restrict__ W, long wst, int K,
                                         float* wsm, U64 c2[][4], int ty, int tx, int tid) {
    int nc = K >> 3;
    st128u(W, wst, 0, wsm, tid);
    for (int c = 0; c < nc; c++) {
        cpwait0();
        __syncthreads();
        if (c + 1 < nc) st128u(W, wst, (c + 1) << 3, wsm + ((c + 1) & 1) * 1088, tid);
        inner128(As, sas, c << 3, wsm + (c & 1) * 1088, c2, ty, tx);
    }
    __syncthreads();
}

__device__ __forceinline__ void fz2(U64* c, int n) {
    for (int i = 0; i < n; i++) c[i] = 0ULL;
}
__device__ __forceinline__ void up2(const U64* c2, float* o) {
    float2 a = unpk(c2[0]), b = unpk(c2[1]);
    o[0] = a.x; o[1] = a.y; o[2] = b.x; o[3] = b.y;
}

template <int SLOTS>
__device__ __forceinline__ void softmax_q(float* buf, int tok, int jq) {
    const int nS = SLOTS / 4;
    float l[nS];
    float m = -1e30f;
#pragma unroll
    for (int i = 0; i < nS; i++) {
        l[i] = buf[tok * 136 + jq * nS + i] * 0.125f;
        m = fmaxf(m, l[i]);
    }
    m = fmaxf(m, __shfl_xor_sync(0xffffffffu, m, 1));
    m = fmaxf(m, __shfl_xor_sync(0xffffffffu, m, 2));
    float s = 0.f;
#pragma unroll
    for (int i = 0; i < nS; i++) { l[i] = expf(l[i] - m); s += l[i]; }
    s += __shfl_xor_sync(0xffffffffu, s, 1);
    s += __shfl_xor_sync(0xffffffffu, s, 2);
    float inv = 1.f / s;
#pragma unroll
    for (int i = 0; i < nS; i++) buf[tok * 136 + jq * nS + i] = l[i] * inv;
}

__global__ void __launch_bounds__(256, 2)
ccg_kernel(
    const float* __restrict__ x_col, const float* __restrict__ pm_state,
    const float* __restrict__ em_state, const float* __restrict__ z_hat_prev,
    const float* __restrict__ ffn_norm_w, const float* __restrict__ ffn_norm_b,
    const float* __restrict__ ffn_up_w, const float* __restrict__ ffn_up_b,
    const float* __restrict__ ffn_down_w, const float* __restrict__ ffn_down_b,
    const float* __restrict__ pm_up_w, const float* __restrict__ pm_up_b,
    const float* __restrict__ pm_down_w, const float* __restrict__ pm_down_b,
    const float* __restrict__ em_up_w, const float* __restrict__ em_up_b,
    const float* __restrict__ em_down_w, const float* __restrict__ em_down_b,
    const float* __restrict__ post_w, const float* __restrict__ post_b,
    const float* __restrict__ enc_w, const float* __restrict__ enc_b,
    const float* __restrict__ pred_w, const float* __restrict__ pred_b,
    const float* __restrict__ gain_w, const float* __restrict__ gain_b,
    float* __restrict__ out)
{
    extern __shared__ float smf[];
    float* xs  = smf;                 // 64 x 132
    float* hs  = xs + 64 * 132;       // 64 x 132
    float* bA  = hs + 64 * 132;       // 64 x 136 (cols 0..67)  -- also FFN gelu buf
    float* bB  = bA + 68;             //             (cols 68..135)
    float* wsm = bA + 64 * 136;       // 2 x 1088 weight staging

    const int tid = threadIdx.x;
    const int ty = tid >> 4, tx = tid & 15;
    const int tok = tid >> 2, jq = tid & 3;
    const int g  = blockIdx.y;
    const int t0 = blockIdx.x * 64;
    const int bs = t0 >> 9;
    const int bidx = g >> 4;

    // ---- load x tile ----
#pragma unroll
    for (int jj = 0; jj < 8; jj++) {
        int flat = tid + 256 * jj;
        int r = flat >> 5, c4 = flat & 31;
        *(float4*)&xs[r * 132 + c4 * 4] =
            *(const float4*)&x_col[((size_t)(t0 + r) * Gn + g) * 128 + c4 * 4];
    }

    // ================= pm memory stage =================
    {
        U64 c2[4][2]; fz2(&c2[0][0], 8);
        gemm64(xs, 132, pm_up_w + (size_t)g * 8192, 64, 128, wsm, c2, ty, tx, tid);
#pragma unroll
        for (int tt = 0; tt < 4; tt++) {
            float o[4]; up2(c2[tt], o);
#pragma unroll
            for (int j = 0; j < 4; j++)
                bB[(ty * 4 + tt) * 136 + tx * 4 + j] = o[j] + pm_up_b[g * 64 + tx * 4 + j];
        }
    }
    const float* Spm = pm_state + (size_t)((bs * 8 + bidx) * 16) * 64;
    {
        U64 c2[4][2]; fz2(&c2[0][0], 8);
        gemm64T(bB, 136, Spm, 16, 64, wsm, c2, ty, tx, tid);
        if (tx < 4) {
#pragma unroll
            for (int tt = 0; tt < 4; tt++) {
                float o[4]; up2(c2[tt], o);
#pragma unroll
                for (int j = 0; j < 4; j++) bA[(ty * 4 + tt) * 136 + tx * 4 + j] = o[j];
            }
        }
    }
    __syncthreads();
    softmax_q<16>(bA, tok, jq);
    __syncthreads();
    {
        U64 c2[4][2]; fz2(&c2[0][0], 8);
        gemm64(bA, 136, Spm, 64, 16, wsm, c2, ty, tx, tid);
#pragma unroll
        for (int tt = 0; tt < 4; tt++) {
            float o[4]; up2(c2[tt], o);
#pragma unroll
            for (int j = 0; j < 4; j++) bB[(ty * 4 + tt) * 136 + tx * 4 + j] = o[j];
        }
    }
    {
        U64 c2[4][4]; fz2(&c2[0][0], 16);
        gemm128(bB, 136, pm_down_w + (size_t)g * 8192, 128, 64, wsm, c2, ty, tx, tid);
#pragma unroll
        for (int tt = 0; tt < 4; tt++) {
            float o0[4], o1[4]; up2(&c2[tt][0], o0); up2(&c2[tt][2], o1);
#pragma unroll
            for (int j = 0; j < 4; j++) {
                int a = tx * 4 + j, b = 64 + tx * 4 + j;
                xs[(ty * 4 + tt) * 132 + a] += o0[j] + pm_down_b[g * 128 + a];
                xs[(ty * 4 + tt) * 132 + b] += o1[j] + pm_down_b[g * 128 + b];
            }
        }
    }

    // ================= em memory stage =================
    {
        U64 c2[4][2]; fz2(&c2[0][0], 8);
        gemm64(xs, 132, em_up_w + (size_t)g * 8192, 64, 128, wsm, c2, ty, tx, tid);
#pragma unroll
        for (int tt = 0; tt < 4; tt++) {
            float o[4]; up2(c2[tt], o);
#pragma unroll
            for (int j = 0; j < 4; j++)
                bB[(ty * 4 + tt) * 136 + tx * 4 + j] = o[j] + em_up_b[g * 64 + tx * 4 + j];
        }
    }
    const float* Sem = em_state + (size_t)((bs * 8 + bidx) * 64) * 64;
    {
        U64 c2[4][2]; fz2(&c2[0][0], 8);
        gemm64T(bB, 136, Sem, 64, 64, wsm, c2, ty, tx, tid);
#pragma unroll
        for (int tt = 0; tt < 4; tt++) {
            float o[4]; up2(c2[tt], o);
#pragma unroll
            for (int j = 0; j < 4; j++) bA[(ty * 4 + tt) * 136 + tx * 4 + j] = o[j];
        }
    }
    __syncthreads();
    softmax_q<64>(bA, tok, jq);
    __syncthreads();
    {
        U64 c2[4][2]; fz2(&c2[0][0], 8);
        gemm64(bA, 136, Sem, 64, 64, wsm, c2, ty, tx, tid);
#pragma unroll
        for (int tt = 0; tt < 4; tt++) {
            float o[4]; up2(c2[tt], o);
#pragma unroll
            for (int j = 0; j < 4; j++) bB[(ty * 4 + tt) * 136 + tx * 4 + j] = o[j];
        }
    }
    {
        U64 c2[4][4]; fz2(&c2[0][0], 16);
        gemm128(bB, 136, em_down_w + (size_t)g * 8192, 128, 64, wsm, c2, ty, tx, tid);
#pragma unroll
        for (int tt = 0; tt < 4; tt++) {
            float o0[4], o1[4]; up2(&c2[tt][0], o0); up2(&c2[tt][2], o1);
#pragma unroll
            for (int j = 0; j < 4; j++) {
                int a = tx * 4 + j, b = 64 + tx * 4 + j;
                xs[(ty * 4 + tt) * 132 + a] += o0[j] + em_down_b[g * 128 + a];
                xs[(ty * 4 + tt) * 132 + b] += o1[j] + em_down_b[g * 128 + b];
            }
        }
    }

    // ================= enc / delta / surprise =================
    {
        U64 c2[4][2]; fz2(&c2[0][0], 8);
        gemm64(xs, 132, enc_w + (size_t)g * 8192, 64, 128, wsm, c2, ty, tx, tid);
        float sp[4];
#pragma unroll
        for (int tt = 0; tt < 4; tt++) {
            int t = ty * 4 + tt;
            size_t tg = t0 + t;
            float o[4]; up2(c2[tt], o);
            float4 zh4 = *(const float4*)&z_hat_prev[(tg * Gn + g) * 64 + tx * 4];
            float z0 = o[0] + enc_b[g * 64 + tx * 4 + 0];
            float z1 = o[1] + enc_b[g * 64 + tx * 4 + 1];
            float z2 = o[2] + enc_b[g * 64 + tx * 4 + 2];
            float z3 = o[3] + enc_b[g * 64 + tx * 4 + 3];
            bA[t * 136 + tx * 4 + 0] = z0; bA[t * 136 + tx * 4 + 1] = z1;
            bA[t * 136 + tx * 4 + 2] = z2; bA[t * 136 + tx * 4 + 3] = z3;
            float e0 = z0 - zh4.x, e1 = z1 - zh4.y, e2 = z2 - zh4.z, e3 = z3 - zh4.w;
            bB[t * 136 + tx * 4 + 0] = e0; bB[t * 136 + tx * 4 + 1] = e1;
            bB[t * 136 + tx * 4 + 2] = e2; bB[t * 136 + tx * 4 + 3] = e3;
            sp[tt] = e0 * e0 + e1 * e1 + e2 * e2 + e3 * e3;
            *(float4*)&out[O_Z + (tg * Gn + g) * 64 + tx * 4] = make_float4(z0, z1, z2, z3);
        }
#pragma unroll
        for (int tt = 0; tt < 4; tt++) {
            sp[tt] += __shfl_xor_sync(0xffffffffu, sp[tt], 1);
            sp[tt] += __shfl_xor_sync(0xffffffffu, sp[tt], 2);
            sp[tt] += __shfl_xor_sync(0xffffffffu, sp[tt], 4);
            sp[tt] += __shfl_xor_sync(0xffffffffu, sp[tt], 8);
        }
        if (tx == 0) {
#pragma unroll
            for (int tt = 0; tt < 4; tt++) {
                size_t tg = t0 + ty * 4 + tt;
                float s = sqrtf(sp[tt]);
                out[O_SURP + tg * Gn + g] = s;
                out[O_S4 + tg * Gn + g] = s;
                out[O_GATE + tg * Gn + g] = fminf(s, 1.f);
            }
        }
    }

    // ================= gain (from delta in bB) =================
    {
        U64 c2[4][4]; fz2(&c2[0][0], 16);
        gemm128(bB, 136, gain_w + (size_t)g * 8192, 128, 64, wsm, c2, ty, tx, tid);
#pragma unroll
        for (int tt = 0; tt < 4; tt++) {
            float o0[4], o1[4]; up2(&c2[tt][0], o0); up2(&c2[tt][2], o1);
#pragma unroll
            for (int j = 0; j < 4; j++) {
                int a = tx * 4 + j, b = 64 + tx * 4 + j;
                hs[(ty * 4 + tt) * 132 + a] = 1.f + 0.1f * tanhf(o0[j] + gain_b[g * 128 + a]);
                hs[(ty * 4 + tt) * 132 + b] = 1.f + 0.1f * tanhf(o1[j] + gain_b[g * 128 + b]);
            }
        }
    }

    // ================= z_hat (from z in bA) — before FFN frees bA =================
    {
        U64 c2[4][2]; fz2(&c2[0][0], 8);
        gemm64(bA, 136, pred_w + (size_t)g * 4096, 64, 64, wsm, c2, ty, tx, tid);
#pragma unroll
        for (int tt = 0; tt < 4; tt++) {
            size_t tg = t0 + ty * 4 + tt;
            float o[4]; up2(c2[tt], o);
            float4 v;
            v.x = o[0] + pred_b[g * 64 + tx * 4 + 0];
            v.y = o[1] + pred_b[g * 64 + tx * 4 + 1];
            v.z = o[2] + pred_b[g * 64 + tx * 4 + 2];
            v.w = o[3] + pred_b[g * 64 + tx * 4 + 3];
            *(float4*)&out[O_ZHAT + (tg * Gn + g) * 64 + tx * 4] = v;
        }
    }
    __syncthreads();

    // ================= layernorm * gain -> hs =================
    {
        float s = 0.f, sq = 0.f;
        float4 xv[8];
#pragma unroll
        for (int u = 0; u < 8; u++) {
            xv[u] = *(const float4*)&xs[tok * 132 + jq * 32 + u * 4];
            s  += xv[u].x + xv[u].y + xv[u].z + xv[u].w;
            sq += xv[u].x * xv[u].x + xv[u].y * xv[u].y + xv[u].z * xv[u].z + xv[u].w * xv[u].w;
        }
        s  += __shfl_xor_sync(0xffffffffu, s, 1);
        s  += __shfl_xor_sync(0xffffffffu, s, 2);
        sq += __shfl_xor_sync(0xffffffffu, sq, 1);
        sq += __shfl_xor_sync(0xffffffffu, sq, 2);
        float mu = s * (1.f / 128.f);
        float rstd = rsqrtf(sq * (1.f / 128.f) - mu * mu + 1e-5f);
#pragma unroll
        for (int u = 0; u < 8; u++) {
            int cb = jq * 32 + u * 4;
            float4 w4 = *(const float4*)&ffn_norm_w[g * 128 + cb];
            float4 b4 = *(const float4*)&ffn_norm_b[g * 128 + cb];
            float4 g4 = *(const float4*)&hs[tok * 132 + cb];
            float4 h4;
            h4.x = ((xv[u].x - mu) * rstd * w4.x + b4.x) * g4.x;
            h4.y = ((xv[u].y - mu) * rstd * w4.y + b4.y) * g4.y;
            h4.z = ((xv[u].z - mu) * rstd * w4.z + b4.z) * g4.z;
            h4.w = ((xv[u].w - mu) * rstd * w4.w + b4.w) * g4.w;
            *(float4*)&hs[tok * 132 + cb] = h4;
        }
    }

    // ================= FFN (gelu buffer = bA region, stride 136) =================
    U64 d2[4][4]; fz2(&d2[0][0], 16);
    for (int ch = 0; ch < 4; ch++) {
        {
            U64 c2[4][4]; fz2(&c2[0][0], 16);
            gemm128(hs, 132, ffn_up_w + (size_t)g * 65536 + ch * 128, 512, 128, wsm, c2, ty, tx, tid);
#pragma unroll
            for (int tt = 0; tt < 4; tt++) {
                float o0[4], o1[4]; up2(&c2[tt][0], o0); up2(&c2[tt][2], o1);
#pragma unroll
                for (int j = 0; j < 4; j++) {
                    float u0 = o0[j] + ffn_up_b[g * 512 + ch * 128 + tx * 4 + j];
                    float u1 = o1[j] + ffn_up_b[g * 512 + ch * 128 + 64 + tx * 4 + j];
                    bA[(ty * 4 + tt) * 136 + tx * 4 + j]      = 0.5f * u0 * (1.f + erff(u0 * 0.70710678f));
                    bA[(ty * 4 + tt) * 136 + 68 + tx * 4 + j] = 0.5f * u1 * (1.f + erff(u1 * 0.70710678f));
                }
            }
        }
        // down: gelu buf has cols 0..63 at offset 0, cols 64..127 at offset 68
        {
            U64 cdum[4][4];
            // accumulate into d2 via two half-K passes over the packed layout
            // first half: K rows 0..63 -> source cols [0..63]
            gemm128(bA, 136, ffn_down_w + (size_t)g * 65536 + (size_t)ch * 128 * 128, 128, 64, wsm, d2, ty, tx, tid);
            // second half: K rows 64..127 -> source cols at +68
            gemm128(bA + 68, 136, ffn_down_w + (size_t)g * 65536 + (size_t)ch * 128 * 128 + 64 * 128, 128, 64, wsm, d2, ty, tx, tid);
            (void)cdum;
        }
    }

    // ================= x_out =================
#pragma unroll
    for (int tt = 0; tt < 4; tt++) {
        int t = ty * 4 + tt;
        size_t tg = t0 + t;
        float o0[4], o1[4]; up2(&d2[tt][0], o0); up2(&d2[tt][2], o1);
        float4 v0, v1;
        int a = tx * 4, b = 64 + tx * 4;
        v0.x = xs[t * 132 + a + 0] + o0[0] + ffn_down_b[g * 128 + a + 0];
        v0.y = xs[t * 132 + a + 1] + o0[1] + ffn_down_b[g * 128 + a + 1];
        v0.z = xs[t * 132 + a + 2] + o0[2] + ffn_down_b[g * 128 + a + 2];
        v0.w = xs[t * 132 + a + 3] + o0[3] + ffn_down_b[g * 128 + a + 3];
        v1.x = xs[t * 132 + b + 0] + o1[0] + ffn_down_b[g * 128 + b + 0];
        v1.y = xs[t * 132 + b + 1] + o1[1] + ffn_down_b[g * 128 + b + 1];
        v1.z = xs[t * 132 + b + 2] + o1[2] + ffn_down_b[g * 128 + b + 2];
        v1.w = xs[t * 132 + b + 3] + o1[3] + ffn_down_b[g * 128 + b + 3];
        *(float4*)&xs[t * 132 + a] = v0;
        *(float4*)&xs[t * 132 + b] = v1;
        *(float4*)&out[O_XOUT + (tg * Gn + g) * 128 + a] = v0;
        *(float4*)&out[O_XOUT + (tg * Gn + g) * 128 + b] = v1;
    }
    __syncthreads();

    // ================= post projection: two 128-wide passes =================
    for (int ph = 0; ph < 2; ph++) {
        U64 c2[4][4]; fz2(&c2[0][0], 16);
        gemm128u(xs, 132, post_w + (size_t)g * 32896 + ph * 128, 257, 128, wsm, c2, ty, tx, tid);
        long long voff = ph ? O_VC : O_VP;
        long long noff = ph ? O_QN : O_KC;
#pragma unroll
        for (int tt = 0; tt < 4; tt++) {
            size_t tg = t0 + ty * 4 + tt;
            float o0[4], o1[4]; up2(&c2[tt][0], o0); up2(&c2[tt][2], o1);
#pragma unroll
            for (int j = 0; j < 4; j++)
                bB[(ty * 4 + tt) * 136 + tx * 4 + j] =
                    o0[j] + post_b[g * 257 + ph * 128 + tx * 4 + j];
            float4 v;
            v.x = o1[0] + post_b[g * 257 + ph * 128 + 64 + tx * 4 + 0];
            v.y = o1[1] + post_b[g * 257 + ph * 128 + 64 + tx * 4 + 1];
            v.z = o1[2] + post_b[g * 257 + ph * 128 + 64 + tx * 4 + 2];
            v.w = o1[3] + post_b[g * 257 + ph * 128 + 64 + tx * 4 + 3];
            *(float4*)&out[voff + (tg * Gn + g) * 64 + tx * 4] = v;
        }
        __syncthreads();
        {
            float4 r4[4];
            float ss = 0.f;
#pragma unroll
            for (int u4 = 0; u4 < 4; u4++) {
                r4[u4] = *(const float4*)&bB[tok * 136 + jq * 16 + u4 * 4];
                ss += r4[u4].x * r4[u4].x + r4[u4].y * r4[u4].y
                    + r4[u4].z * r4[u4].z + r4[u4].w * r4[u4].w;
            }
            ss += __shfl_xor_sync(0xffffffffu, ss, 1);
            ss += __shfl_xor_sync(0xffffffffu, ss, 2);
            float inv = 1.f / (sqrtf(ss) + 1e-6f);
            size_t tg = t0 + tok;
#pragma unroll
            for (int u4 = 0; u4 < 4; u4++) {
                float4 v;
                v.x = r4[u4].x * inv; v.y = r4[u4].y * inv;
                v.z = r4[u4].z * inv; v.w = r4[u4].w * inv;
                *(float4*)&out[noff + (tg * Gn + g) * 64 + jq * 16 + u4 * 4] = v;
            }
        }
        __syncthreads();
    }

    // ================= w_nov (proj column 256) =================
    if (tid < 128)
        wsm[tid] = post_w[(size_t)g * 32896 + (size_t)tid * 257 + 256];
    __syncthreads();
    {
        float acc = 0.f;
#pragma unroll
        for (int u = 0; u < 8; u++) {
            float4 xv = *(const float4*)&xs[tok * 132 + jq * 32 + u * 4];
            float4 wv = *(const float4*)&wsm[jq * 32 + u * 4];
            acc += xv.x * wv.x + xv.y * wv.y + xv.z * wv.z + xv.w * wv.w;
        }
        acc += __shfl_xor_sync(0xffffffffu, acc, 1);
        acc += __shfl_xor_sync(0xffffffffu, acc, 2);
        if (jq == 0) {
            size_t tg = t0 + tok;
            float nv = acc + post_b[g * 257 + 256];
            out[O_WN + tg * Gn + g] = 1.f / (1.f + expf(-nv));
        }
    }
}

extern "C" void kernel_launch(void* const* d_in, const int* in_sizes, int n_in,
                              void* d_out, int out_size) {
    const float* x_col      = (const float*)d_in[0];
    const float* pm_state   = (const float*)d_in[1];
    const float* em_state   = (const float*)d_in[2];
    const float* z_hat_prev = (const float*)d_in[3];
    const float* ffn_norm_w = (const float*)d_in[4];
    const float* ffn_norm_b = (const float*)d_in[5];
    const float* ffn_up_w   = (const float*)d_in[6];
    const float* ffn_up_b   = (const float*)d_in[7];
    const float* ffn_down_w = (const float*)d_in[8];
    const float* ffn_down_b = (const float*)d_in[9];
    const float* pm_up_w    = (const float*)d_in[10];
    const float* pm_up_b    = (const float*)d_in[11];
    const float* pm_down_w  = (const float*)d_in[12];
    const float* pm_down_b  = (const float*)d_in[13];
    const float* em_up_w    = (const float*)d_in[14];
    const float* em_up_b    = (const float*)d_in[15];
    const float* em_down_w  = (const float*)d_in[16];
    const float* em_down_b  = (const float*)d_in[17];
    const float* post_w     = (const float*)d_in[18];
    const float* post_b     = (const float*)d_in[19];
    const float* enc_w      = (const float*)d_in[20];
    const float* enc_b      = (const float*)d_in[21];
    const float* pred_w     = (const float*)d_in[22];
    const float* pred_b     = (const float*)d_in[23];
    const float* gain_w     = (const float*)d_in[24];
    const float* gain_b     = (const float*)d_in[25];
    float* out = (float*)d_out;

    const int smem = (64 * 132 * 2 + 64 * 136 + 2 * 1088) * 4;  // 111104 B
    cudaFuncSetAttribute(ccg_kernel, cudaFuncAttributeMaxDynamicSharedMemorySize, smem);
    dim3 grid(32, 128);
    ccg_kernel<<<grid, 256, smem>>>(
        x_col, pm_state, em_state, z_hat_prev,
        ffn_norm_w, ffn_norm_b, ffn_up_w, ffn_up_b, ffn_down_w, ffn_down_b,
        pm_up_w, pm_up_b, pm_down_w, pm_down_b,
        em_up_w, em_up_b, em_down_w, em_down_b,
        post_w, post_b, enc_w, enc_b, pred_w, pred_b, gain_w, gain_b,
        out);
}

// round 5
// speedup vs baseline: 1.2794x; 1.0012x over previous
#include <cuda_runtime.h>
#include <math.h>

#define Gn 128
typedef unsigned long long U64;

static const long long O_XOUT = 0LL;
static const long long O_Z    = 33554432LL;
static const long long O_ZHAT = 50331648LL;
static const long long O_SURP = 67108864LL;
static const long long O_KC   = 67371008LL;
static const long long O_VP   = 84148224LL;
static const long long O_GATE = 100925440LL;
static const long long O_QN   = 101187584LL;
static const long long O_VC   = 117964800LL;
static const long long O_WN   = 134742016LL;
static const long long O_S4   = 135004160LL;

__device__ __forceinline__ void f2fma(U64& d, U64 a, U64 b) {
    asm("fma.rn.f32x2 %0, %1, %2, %0;" : "+l"(d) : "l"(a), "l"(b));
}
__device__ __forceinline__ U64 dup2(float a) {
    U64 r; asm("mov.b64 %0, {%1, %1};" : "=l"(r) : "f"(a)); return r;
}
__device__ __forceinline__ float2 unpk(U64 v) {
    float2 f; asm("mov.b64 {%0, %1}, %2;" : "=f"(f.x), "=f"(f.y) : "l"(v)); return f;
}
__device__ __forceinline__ void cpa16(float* dst, const float* src) {
    unsigned d = (unsigned)__cvta_generic_to_shared(dst);
    asm volatile("cp.async.ca.shared.global [%0], [%1], 16;" :: "r"(d), "l"(src) : "memory");
}
__device__ __forceinline__ void cpa4(float* dst, const float* src) {
    unsigned d = (unsigned)__cvta_generic_to_shared(dst);
    asm volatile("cp.async.ca.shared.global [%0], [%1], 4;" :: "r"(d), "l"(src) : "memory");
}
__device__ __forceinline__ void cpcommit() { asm volatile("cp.async.commit_group;" ::: "memory"); }
__device__ __forceinline__ void cpwait0()  { asm volatile("cp.async.wait_group 0;" ::: "memory"); }

// ---------- staging ----------
// 16 k-rows x 64 cols -> buf stride 68
__device__ __forceinline__ void st64(const float* __restrict__ W, long wst, int k0,
                                     float* buf, int tid) {
    int r = tid >> 4, cc = tid & 15;
    cpa16(&buf[r * 68 + cc * 4], &W[(size_t)(k0 + r) * wst + cc * 4]);
    cpcommit();
}
// 8 k-rows x 128 cols -> buf stride 136 (two 68-halves)
__device__ __forceinline__ void st128(const float* __restrict__ W, long wst, int k0,
                                      float* buf, int tid) {
    int r = tid >> 5, c = tid & 31;
    int half = c >> 4, c4 = c & 15;
    cpa16(&buf[r * 136 + half * 68 + c4 * 4], &W[(size_t)(k0 + r) * wst + c * 4]);
    cpcommit();
}
// same, 4B-aligned source (post_w, stride 257)
__device__ __forceinline__ void st128u(const float* __restrict__ W, long wst, int k0,
                                       float* buf, int tid) {
#pragma unroll
    for (int j = 0; j < 4; j++) {
        int flat = tid + 256 * j;
        int r = flat >> 7, col = flat & 127;
        cpa4(&buf[r * 136 + col + ((col >> 6) << 2)], &W[(size_t)(k0 + r) * wst + col]);
    }
    cpcommit();
}

// ---------- GEMM cores (f32x2) ----------
__device__ __forceinline__ void inner64(const float* __restrict__ As, int sas, int k0,
                                        const float* wb, U64 c2[][2], int ty, int tx) {
#pragma unroll
    for (int i4 = 0; i4 < 4; i4++) {
        float4 a4[4];
#pragma unroll
        for (int tt = 0; tt < 4; tt++)
            a4[tt] = *(const float4*)&As[(ty * 4 + tt) * sas + k0 + i4 * 4];
#pragma unroll
        for (int ii = 0; ii < 4; ii++) {
            ulonglong2 w = *(const ulonglong2*)&wb[(i4 * 4 + ii) * 68 + tx * 4];
#pragma unroll
            for (int tt = 0; tt < 4; tt++) {
                U64 a = dup2(((const float*)&a4[tt])[ii]);
                f2fma(c2[tt][0], a, w.x);
                f2fma(c2[tt][1], a, w.y);
            }
        }
    }
}

__device__ __forceinline__ void gemm64(const float* __restrict__ As, int sas,
                                       const float* __restrict__ W, long wst, int K,
                                       float* wsm, U64 c2[][2], int ty, int tx, int tid) {
    int nc = K >> 4;
    st64(W, wst, 0, wsm, tid);
    for (int c = 0; c < nc; c++) {
        cpwait0();
        __syncthreads();
        if (c + 1 < nc) st64(W, wst, (c + 1) << 4, wsm + ((c + 1) & 1) * 1088, tid);
        inner64(As, sas, c << 4, wsm + (c & 1) * 1088, c2, ty, tx);
    }
    __syncthreads();
}

// transposed-B staging (attention logits): W[k][s] = S[s][k]
__device__ __forceinline__ void gemm64T(const float* __restrict__ As, int sas,
                                        const float* __restrict__ S, int slots, int K,
                                        float* wsm, U64 c2[][2], int ty, int tx, int tid) {
    for (int k0 = 0; k0 < K; k0 += 16) {
        int s = tid & 63, k4 = tid >> 6;
        float4 v = make_float4(0.f, 0.f, 0.f, 0.f);
        if (s < slots) v = *(const float4*)&S[s * 64 + k0 + k4 * 4];
        __syncthreads();
        wsm[(k4 * 4 + 0) * 68 + s] = v.x;
        wsm[(k4 * 4 + 1) * 68 + s] = v.y;
        wsm[(k4 * 4 + 2) * 68 + s] = v.z;
        wsm[(k4 * 4 + 3) * 68 + s] = v.w;
        __syncthreads();
        inner64(As, sas, k0, wsm, c2, ty, tx);
    }
    __syncthreads();
}

__device__ __forceinline__ void inner128(const float* __restrict__ As, int sas, int k0,
                                         const float* wb, U64 c2[][4], int ty, int tx) {
#pragma unroll
    for (int i4 = 0; i4 < 2; i4++) {
        float4 a4[4];
#pragma unroll
        for (int tt = 0; tt < 4; tt++)
            a4[tt] = *(const float4*)&As[(ty * 4 + tt) * sas + k0 + i4 * 4];
#pragma unroll
        for (int ii = 0; ii < 4; ii++) {
            ulonglong2 w0 = *(const ulonglong2*)&wb[(i4 * 4 + ii) * 136 + tx * 4];
            ulonglong2 w1 = *(const ulonglong2*)&wb[(i4 * 4 + ii) * 136 + 68 + tx * 4];
#pragma unroll
            for (int tt = 0; tt < 4; tt++) {
                U64 a = dup2(((const float*)&a4[tt])[ii]);
                f2fma(c2[tt][0], a, w0.x);
                f2fma(c2[tt][1], a, w0.y);
                f2fma(c2[tt][2], a, w1.x);
                f2fma(c2[tt][3], a, w1.y);
            }
        }
    }
}

__device__ __forceinline__ void gemm128(const float* __restrict__ As, int sas,
                                        const float* __restrict__ W, long wst, int K,
                                        float* wsm, U64 c2[][4], int ty, int tx, int tid) {
    int nc = K >> 3;
    st128(W, wst, 0, wsm, tid);
    for (int c = 0; c < nc; c++) {
        cpwait0();
        __syncthreads();
        if (c + 1 < nc) st128(W, wst, (c + 1) << 3, wsm + ((c + 1) & 1) * 1088, tid);
        inner128(As, sas, c << 3, wsm + (c & 1) * 1088, c2, ty, tx);
    }
    __syncthreads();
}

__device__ __forceinline__ void gemm128u(const float* __restrict__ As, int sas,
                                         const float* __restrict__ W, long wst, int K,
                                         float* wsm, U64 c2[][4], int ty, int tx, int tid) {
    int nc = K >> 3;
    st128u(W, wst, 0, wsm, tid);
    for (int c = 0; c < nc; c++) {
        cpwait0();
        __syncthreads();
        if (c + 1 < nc) st128u(W, wst, (c + 1) << 3, wsm + ((c + 1) & 1) * 1088, tid);
        inner128(As, sas, c << 3, wsm + (c & 1) * 1088, c2, ty, tx);
    }
    __syncthreads();
}

__device__ __forceinline__ void fz2(U64* c, int n) {
    for (int i = 0; i < n; i++) c[i] = 0ULL;
}
__device__ __forceinline__ void up2(const U64* c2, float* o) {
    float2 a = unpk(c2[0]), b = unpk(c2[1]);
    o[0] = a.x; o[1] = a.y; o[2] = b.x; o[3] = b.y;
}

template <int SLOTS>
__device__ __forceinline__ void softmax_q(float* buf, int tok, int jq) {
    const int nS = SLOTS / 4;
    float l[nS];
    float m = -1e30f;
#pragma unroll
    for (int i = 0; i < nS; i++) {
        l[i] = buf[tok * 136 + jq * nS + i] * 0.125f;
        m = fmaxf(m, l[i]);
    }
    m = fmaxf(m, __shfl_xor_sync(0xffffffffu, m, 1));
    m = fmaxf(m, __shfl_xor_sync(0xffffffffu, m, 2));
    float s = 0.f;
#pragma unroll
    for (int i = 0; i < nS; i++) { l[i] = expf(l[i] - m); s += l[i]; }
    s += __shfl_xor_sync(0xffffffffu, s, 1);
    s += __shfl_xor_sync(0xffffffffu, s, 2);
    float inv = 1.f / s;
#pragma unroll
    for (int i = 0; i < nS; i++) buf[tok * 136 + jq * nS + i] = l[i] * inv;
}

__global__ void __launch_bounds__(256, 2)
ccg_kernel(
    const float* __restrict__ x_col, const float* __restrict__ pm_state,
    const float* __restrict__ em_state, const float* __restrict__ z_hat_prev,
    const float* __restrict__ ffn_norm_w, const float* __restrict__ ffn_norm_b,
    const float* __restrict__ ffn_up_w, const float* __restrict__ ffn_up_b,
    const float* __restrict__ ffn_down_w, const float* __restrict__ ffn_down_b,
    const float* __restrict__ pm_up_w, const float* __restrict__ pm_up_b,
    const float* __restrict__ pm_down_w, const float* __restrict__ pm_down_b,
    const float* __restrict__ em_up_w, const float* __restrict__ em_up_b,
    const float* __restrict__ em_down_w, const float* __restrict__ em_down_b,
    const float* __restrict__ post_w, const float* __restrict__ post_b,
    const float* __restrict__ enc_w, const float* __restrict__ enc_b,
    const float* __restrict__ pred_w, const float* __restrict__ pred_b,
    const float* __restrict__ gain_w, const float* __restrict__ gain_b,
    float* __restrict__ out)
{
    extern __shared__ float smf[];
    float* xs  = smf;                 // 64 x 132
    float* hs  = xs + 64 * 132;       // 64 x 132
    float* bA  = hs + 64 * 132;       // 64 x 136 (cols 0..67)  -- also FFN gelu buf
    float* bB  = bA + 68;             //             (cols 68..135)
    float* wsm = bA + 64 * 136;       // 2 x 1088 weight staging

    const int tid = threadIdx.x;
    const int ty = tid >> 4, tx = tid & 15;
    const int tok = tid >> 2, jq = tid & 3;
    const int g  = blockIdx.y;
    const int t0 = blockIdx.x * 64;
    const int bs = t0 >> 9;
    const int bidx = g >> 4;

    // ---- load x tile ----
#pragma unroll
    for (int jj = 0; jj < 8; jj++) {
        int flat = tid + 256 * jj;
        int r = flat >> 5, c4 = flat & 31;
        *(float4*)&xs[r * 132 + c4 * 4] =
            *(const float4*)&x_col[((size_t)(t0 + r) * Gn + g) * 128 + c4 * 4];
    }

    // ================= pm memory stage =================
    {
        U64 c2[4][2]; fz2(&c2[0][0], 8);
        gemm64(xs, 132, pm_up_w + (size_t)g * 8192, 64, 128, wsm, c2, ty, tx, tid);
#pragma unroll
        for (int tt = 0; tt < 4; tt++) {
            float o[4]; up2(c2[tt], o);
#pragma unroll
            for (int j = 0; j < 4; j++)
                bB[(ty * 4 + tt) * 136 + tx * 4 + j] = o[j] + pm_up_b[g * 64 + tx * 4 + j];
        }
    }
    const float* Spm = pm_state + (size_t)((bs * 8 + bidx) * 16) * 64;
    {
        U64 c2[4][2]; fz2(&c2[0][0], 8);
        gemm64T(bB, 136, Spm, 16, 64, wsm, c2, ty, tx, tid);
        if (tx < 4) {
#pragma unroll
            for (int tt = 0; tt < 4; tt++) {
                float o[4]; up2(c2[tt], o);
#pragma unroll
                for (int j = 0; j < 4; j++) bA[(ty * 4 + tt) * 136 + tx * 4 + j] = o[j];
            }
        }
    }
    __syncthreads();
    softmax_q<16>(bA, tok, jq);
    __syncthreads();
    {
        U64 c2[4][2]; fz2(&c2[0][0], 8);
        gemm64(bA, 136, Spm, 64, 16, wsm, c2, ty, tx, tid);
#pragma unroll
        for (int tt = 0; tt < 4; tt++) {
            float o[4]; up2(c2[tt], o);
#pragma unroll
            for (int j = 0; j < 4; j++) bB[(ty * 4 + tt) * 136 + tx * 4 + j] = o[j];
        }
    }
    {
        U64 c2[4][4]; fz2(&c2[0][0], 16);
        gemm128(bB, 136, pm_down_w + (size_t)g * 8192, 128, 64, wsm, c2, ty, tx, tid);
#pragma unroll
        for (int tt = 0; tt < 4; tt++) {
            float o0[4], o1[4]; up2(&c2[tt][0], o0); up2(&c2[tt][2], o1);
#pragma unroll
            for (int j = 0; j < 4; j++) {
                int a = tx * 4 + j, b = 64 + tx * 4 + j;
                xs[(ty * 4 + tt) * 132 + a] += o0[j] + pm_down_b[g * 128 + a];
                xs[(ty * 4 + tt) * 132 + b] += o1[j] + pm_down_b[g * 128 + b];
            }
        }
    }

    // ================= em memory stage =================
    {
        U64 c2[4][2]; fz2(&c2[0][0], 8);
        gemm64(xs, 132, em_up_w + (size_t)g * 8192, 64, 128, wsm, c2, ty, tx, tid);
#pragma unroll
        for (int tt = 0; tt < 4; tt++) {
            float o[4]; up2(c2[tt], o);
#pragma unroll
            for (int j = 0; j < 4; j++)
                bB[(ty * 4 + tt) * 136 + tx * 4 + j] = o[j] + em_up_b[g * 64 + tx * 4 + j];
        }
    }
    const float* Sem = em_state + (size_t)((bs * 8 + bidx) * 64) * 64;
    {
        U64 c2[4][2]; fz2(&c2[0][0], 8);
        gemm64T(bB, 136, Sem, 64, 64, wsm, c2, ty, tx, tid);
#pragma unroll
        for (int tt = 0; tt < 4; tt++) {
            float o[4]; up2(c2[tt], o);
#pragma unroll
            for (int j = 0; j < 4; j++) bA[(ty * 4 + tt) * 136 + tx * 4 + j] = o[j];
        }
    }
    __syncthreads();
    softmax_q<64>(bA, tok, jq);
    __syncthreads();
    {
        U64 c2[4][2]; fz2(&c2[0][0], 8);
        gemm64(bA, 136, Sem, 64, 64, wsm, c2, ty, tx, tid);
#pragma unroll
        for (int tt = 0; tt < 4; tt++) {
            float o[4]; up2(c2[tt], o);
#pragma unroll
            for (int j = 0; j < 4; j++) bB[(ty * 4 + tt) * 136 + tx * 4 + j] = o[j];
        }
    }
    {
        U64 c2[4][4]; fz2(&c2[0][0], 16);
        gemm128(bB, 136, em_down_w + (size_t)g * 8192, 128, 64, wsm, c2, ty, tx, tid);
#pragma unroll
        for (int tt = 0; tt < 4; tt++) {
            float o0[4], o1[4]; up2(&c2[tt][0], o0); up2(&c2[tt][2], o1);
#pragma unroll
            for (int j = 0; j < 4; j++) {
                int a = tx * 4 + j, b = 64 + tx * 4 + j;
                xs[(ty * 4 + tt) * 132 + a] += o0[j] + em_down_b[g * 128 + a];
                xs[(ty * 4 + tt) * 132 + b] += o1[j] + em_down_b[g * 128 + b];
            }
        }
    }

    // ================= enc / delta / surprise =================
    {
        U64 c2[4][2]; fz2(&c2[0][0], 8);
        gemm64(xs, 132, enc_w + (size_t)g * 8192, 64, 128, wsm, c2, ty, tx, tid);
        float sp[4];
#pragma unroll
        for (int tt = 0; tt < 4; tt++) {
            int t = ty * 4 + tt;
            size_t tg = t0 + t;
            float o[4]; up2(c2[tt], o);
            float4 zh4 = *(const float4*)&z_hat_prev[(tg * Gn + g) * 64 + tx * 4];
            float z0 = o[0] + enc_b[g * 64 + tx * 4 + 0];
            float z1 = o[1] + enc_b[g * 64 + tx * 4 + 1];
            float z2 = o[2] + enc_b[g * 64 + tx * 4 + 2];
            float z3 = o[3] + enc_b[g * 64 + tx * 4 + 3];
            bA[t * 136 + tx * 4 + 0] = z0; bA[t * 136 + tx * 4 + 1] = z1;
            bA[t * 136 + tx * 4 + 2] = z2; bA[t * 136 + tx * 4 + 3] = z3;
            float e0 = z0 - zh4.x, e1 = z1 - zh4.y, e2 = z2 - zh4.z, e3 = z3 - zh4.w;
            bB[t * 136 + tx * 4 + 0] = e0; bB[t * 136 + tx * 4 + 1] = e1;
            bB[t * 136 + tx * 4 + 2] = e2; bB[t * 136 + tx * 4 + 3] = e3;
            sp[tt] = e0 * e0 + e1 * e1 + e2 * e2 + e3 * e3;
            *(float4*)&out[O_Z + (tg * Gn + g) * 64 + tx * 4] = make_float4(z0, z1, z2, z3);
        }
#pragma unroll
        for (int tt = 0; tt < 4; tt++) {
            sp[tt] += __shfl_xor_sync(0xffffffffu, sp[tt], 1);
            sp[tt] += __shfl_xor_sync(0xffffffffu, sp[tt], 2);
            sp[tt] += __shfl_xor_sync(0xffffffffu, sp[tt], 4);
            sp[tt] += __shfl_xor_sync(0xffffffffu, sp[tt], 8);
        }
        if (tx == 0) {
#pragma unroll
            for (int tt = 0; tt < 4; tt++) {
                size_t tg = t0 + ty * 4 + tt;
                float s = sqrtf(sp[tt]);
                out[O_SURP + tg * Gn + g] = s;
                out[O_S4 + tg * Gn + g] = s;
                out[O_GATE + tg * Gn + g] = fminf(s, 1.f);
            }
        }
    }

    // ================= gain (from delta in bB) =================
    {
        U64 c2[4][4]; fz2(&c2[0][0], 16);
        gemm128(bB, 136, gain_w + (size_t)g * 8192, 128, 64, wsm, c2, ty, tx, tid);
#pragma unroll
        for (int tt = 0; tt < 4; tt++) {
            float o0[4], o1[4]; up2(&c2[tt][0], o0); up2(&c2[tt][2], o1);
#pragma unroll
            for (int j = 0; j < 4; j++) {
                int a = tx * 4 + j, b = 64 + tx * 4 + j;
                hs[(ty * 4 + tt) * 132 + a] = 1.f + 0.1f * tanhf(o0[j] + gain_b[g * 128 + a]);
                hs[(ty * 4 + tt) * 132 + b] = 1.f + 0.1f * tanhf(o1[j] + gain_b[g * 128 + b]);
            }
        }
    }

    // ================= z_hat (from z in bA) — before FFN frees bA =================
    {
        U64 c2[4][2]; fz2(&c2[0][0], 8);
        gemm64(bA, 136, pred_w + (size_t)g * 4096, 64, 64, wsm, c2, ty, tx, tid);
#pragma unroll
        for (int tt = 0; tt < 4; tt++) {
            size_t tg = t0 + ty * 4 + tt;
            float o[4]; up2(c2[tt], o);
            float4 v;
            v.x = o[0] + pred_b[g * 64 + tx * 4 + 0];
            v.y = o[1] + pred_b[g * 64 + tx * 4 + 1];
            v.z = o[2] + pred_b[g * 64 + tx * 4 + 2];
            v.w = o[3] + pred_b[g * 64 + tx * 4 + 3];
            *(float4*)&out[O_ZHAT + (tg * Gn + g) * 64 + tx * 4] = v;
        }
    }
    __syncthreads();

    // ================= layernorm * gain -> hs =================
    {
        float s = 0.f, sq = 0.f;
        float4 xv[8];
#pragma unroll
        for (int u = 0; u < 8; u++) {
            xv[u] = *(const float4*)&xs[tok * 132 + jq * 32 + u * 4];
            s  += xv[u].x + xv[u].y + xv[u].z + xv[u].w;
            sq += xv[u].x * xv[u].x + xv[u].y * xv[u].y + xv[u].z * xv[u].z + xv[u].w * xv[u].w;
        }
        s  += __shfl_xor_sync(0xffffffffu, s, 1);
        s  += __shfl_xor_sync(0xffffffffu, s, 2);
        sq += __shfl_xor_sync(0xffffffffu, sq, 1);
        sq += __shfl_xor_sync(0xffffffffu, sq, 2);
        float mu = s * (1.f / 128.f);
        float rstd = rsqrtf(sq * (1.f / 128.f) - mu * mu + 1e-5f);
#pragma unroll
        for (int u = 0; u < 8; u++) {
            int cb = jq * 32 + u * 4;
            float4 w4 = *(const float4*)&ffn_norm_w[g * 128 + cb];
            float4 b4 = *(const float4*)&ffn_norm_b[g * 128 + cb];
            float4 g4 = *(const float4*)&hs[tok * 132 + cb];
            float4 h4;
            h4.x = ((xv[u].x - mu) * rstd * w4.x + b4.x) * g4.x;
            h4.y = ((xv[u].y - mu) * rstd * w4.y + b4.y) * g4.y;
            h4.z = ((xv[u].z - mu) * rstd * w4.z + b4.z) * g4.z;
            h4.w = ((xv[u].w - mu) * rstd * w4.w + b4.w) * g4.w;
            *(float4*)&hs[tok * 132 + cb] = h4;
        }
    }

    // ================= FFN (gelu buffer = bA region, stride 136) =================
    U64 d2[4][4]; fz2(&d2[0][0], 16);
    for (int ch = 0; ch < 4; ch++) {
        {
            U64 c2[4][4]; fz2(&c2[0][0], 16);
            gemm128(hs, 132, ffn_up_w + (size_t)g * 65536 + ch * 128, 512, 128, wsm, c2, ty, tx, tid);
#pragma unroll
            for (int tt = 0; tt < 4; tt++) {
                float o0[4], o1[4]; up2(&c2[tt][0], o0); up2(&c2[tt][2], o1);
#pragma unroll
                for (int j = 0; j < 4; j++) {
                    float u0 = o0[j] + ffn_up_b[g * 512 + ch * 128 + tx * 4 + j];
                    float u1 = o1[j] + ffn_up_b[g * 512 + ch * 128 + 64 + tx * 4 + j];
                    bA[(ty * 4 + tt) * 136 + tx * 4 + j]      = 0.5f * u0 * (1.f + erff(u0 * 0.70710678f));
                    bA[(ty * 4 + tt) * 136 + 68 + tx * 4 + j] = 0.5f * u1 * (1.f + erff(u1 * 0.70710678f));
                }
            }
        }
        // down: gelu buf has cols 0..63 at offset 0, cols 64..127 at offset 68
        {
            U64 cdum[4][4];
            // accumulate into d2 via two half-K passes over the packed layout
            // first half: K rows 0..63 -> source cols [0..63]
            gemm128(bA, 136, ffn_down_w + (size_t)g * 65536 + (size_t)ch * 128 * 128, 128, 64, wsm, d2, ty, tx, tid);
            // second half: K rows 64..127 -> source cols at +68
            gemm128(bA + 68, 136, ffn_down_w + (size_t)g * 65536 + (size_t)ch * 128 * 128 + 64 * 128, 128, 64, wsm, d2, ty, tx, tid);
            (void)cdum;
        }
    }

    // ================= x_out =================
#pragma unroll
    for (int tt = 0; tt < 4; tt++) {
        int t = ty * 4 + tt;
        size_t tg = t0 + t;
        float o0[4], o1[4]; up2(&d2[tt][0], o0); up2(&d2[tt][2], o1);
        float4 v0, v1;
        int a = tx * 4, b = 64 + tx * 4;
        v0.x = xs[t * 132 + a + 0] + o0[0] + ffn_down_b[g * 128 + a + 0];
        v0.y = xs[t * 132 + a + 1] + o0[1] + ffn_down_b[g * 128 + a + 1];
        v0.z = xs[t * 132 + a + 2] + o0[2] + ffn_down_b[g * 128 + a + 2];
        v0.w = xs[t * 132 + a + 3] + o0[3] + ffn_down_b[g * 128 + a + 3];
        v1.x = xs[t * 132 + b + 0] + o1[0] + ffn_down_b[g * 128 + b + 0];
        v1.y = xs[t * 132 + b + 1] + o1[1] + ffn_down_b[g * 128 + b + 1];
        v1.z = xs[t * 132 + b + 2] + o1[2] + ffn_down_b[g * 128 + b + 2];
        v1.w = xs[t * 132 + b + 3] + o1[3] + ffn_down_b[g * 128 + b + 3];
        *(float4*)&xs[t * 132 + a] = v0;
        *(float4*)&xs[t * 132 + b] = v1;
        *(float4*)&out[O_XOUT + (tg * Gn + g) * 128 + a] = v0;
        *(float4*)&out[O_XOUT + (tg * Gn + g) * 128 + b] = v1;
    }
    __syncthreads();

    // ================= post projection: two 128-wide passes =================
    for (int ph = 0; ph < 2; ph++) {
        U64 c2[4][4]; fz2(&c2[0][0], 16);
        gemm128u(xs, 132, post_w + (size_t)g * 32896 + ph * 128, 257, 128, wsm, c2, ty, tx, tid);
        long long voff = ph ? O_VC : O_VP;
        long long noff = ph ? O_QN : O_KC;
#pragma unroll
        for (int tt = 0; tt < 4; tt++) {
            size_t tg = t0 + ty * 4 + tt;
            float o0[4], o1[4]; up2(&c2[tt][0], o0); up2(&c2[tt][2], o1);
#pragma unroll
            for (int j = 0; j < 4; j++)
                bB[(ty * 4 + tt) * 136 + tx * 4 + j] =
                    o0[j] + post_b[g * 257 + ph * 128 + tx * 4 + j];
            float4 v;
            v.x = o1[0] + post_b[g * 257 + ph * 128 + 64 + tx * 4 + 0];
            v.y = o1[1] + post_b[g * 257 + ph * 128 + 64 + tx * 4 + 1];
            v.z = o1[2] + post_b[g * 257 + ph * 128 + 64 + tx * 4 + 2];
            v.w = o1[3] + post_b[g * 257 + ph * 128 + 64 + tx * 4 + 3];
            *(float4*)&out[voff + (tg * Gn + g) * 64 + tx * 4] = v;
        }
        __syncthreads();
        {
            float4 r4[4];
            float ss = 0.f;
#pragma unroll
            for (int u4 = 0; u4 < 4; u4++) {
                r4[u4] = *(const float4*)&bB[tok * 136 + jq * 16 + u4 * 4];
                ss += r4[u4].x * r4[u4].x + r4[u4].y * r4[u4].y
                    + r4[u4].z * r4[u4].z + r4[u4].w * r4[u4].w;
            }
            ss += __shfl_xor_sync(0xffffffffu, ss, 1);
            ss += __shfl_xor_sync(0xffffffffu, ss, 2);
            float inv = 1.f / (sqrtf(ss) + 1e-6f);
            size_t tg = t0 + tok;
#pragma unroll
            for (int u4 = 0; u4 < 4; u4++) {
                float4 v;
                v.x = r4[u4].x * inv; v.y = r4[u4].y * inv;
                v.z = r4[u4].z * inv; v.w = r4[u4].w * inv;
                *(float4*)&out[noff + (tg * Gn + g) * 64 + jq * 16 + u4 * 4] = v;
            }
        }
        __syncthreads();
    }

    // ================= w_nov (proj column 256) =================
    if (tid < 128)
        wsm[tid] = post_w[(size_t)g * 32896 + (size_t)tid * 257 + 256];
    __syncthreads();
    {
        float acc = 0.f;
#pragma unroll
        for (int u = 0; u < 8; u++) {
            float4 xv = *(const float4*)&xs[tok * 132 + jq * 32 + u * 4];
            float4 wv = *(const float4*)&wsm[jq * 32 + u * 4];
            acc += xv.x * wv.x + xv.y * wv.y + xv.z * wv.z + xv.w * wv.w;
        }
        acc += __shfl_xor_sync(0xffffffffu, acc, 1);
        acc += __shfl_xor_sync(0xffffffffu, acc, 2);
        if (jq == 0) {
            size_t tg = t0 + tok;
            float nv = acc + post_b[g * 257 + 256];
            out[O_WN + tg * Gn + g] = 1.f / (1.f + expf(-nv));
        }
    }
}

extern "C" void kernel_launch(void* const* d_in, const int* in_sizes, int n_in,
                              void* d_out, int out_size) {
    const float* x_col      = (const float*)d_in[0];
    const float* pm_state   = (const float*)d_in[1];
    const float* em_state   = (const float*)d_in[2];
    const float* z_hat_prev = (const float*)d_in[3];
    const float* ffn_norm_w = (const float*)d_in[4];
    const float* ffn_norm_b = (const float*)d_in[5];
    const float* ffn_up_w   = (const float*)d_in[6];
    const float* ffn_up_b   = (const float*)d_in[7];
    const float* ffn_down_w = (const float*)d_in[8];
    const float* ffn_down_b = (const float*)d_in[9];
    const float* pm_up_w    = (const float*)d_in[10];
    const float* pm_up_b    = (const float*)d_in[11];
    const float* pm_down_w  = (const float*)d_in[12];
    const float* pm_down_b  = (const float*)d_in[13];
    const float* em_up_w    = (const float*)d_in[14];
    const float* em_up_b    = (const float*)d_in[15];
    const float* em_down_w  = (const float*)d_in[16];
    const float* em_down_b  = (const float*)d_in[17];
    const float* post_w     = (const float*)d_in[18];
    const float* post_b     = (const float*)d_in[19];
    const float* enc_w      = (const float*)d_in[20];
    const float* enc_b      = (const float*)d_in[21];
    const float* pred_w     = (const float*)d_in[22];
    const float* pred_b     = (const float*)d_in[23];
    const float* gain_w     = (const float*)d_in[24];
    const float* gain_b     = (const float*)d_in[25];
    float* out = (float*)d_out;

    const int smem = (64 * 132 * 2 + 64 * 136 + 2 * 1088) * 4;  // 111104 B
    cudaFuncSetAttribute(ccg_kernel, cudaFuncAttributeMaxDynamicSharedMemorySize, smem);
    dim3 grid(32, 128);
    ccg_kernel<<<grid, 256, smem>>>(
        x_col, pm_state, em_state, z_hat_prev,
        ffn_norm_w, ffn_norm_b, ffn_up_w, ffn_up_b, ffn_down_w, ffn_down_b,
        pm_up_w, pm_up_b, pm_down_w, pm_down_b,
        em_up_w, em_up_b, em_down_w, em_down_b,
        post_w, post_b, enc_w, enc_b, pred_w, pred_b, gain_w, gain_b,
        out);
}